// round 2
// baseline (speedup 1.0000x reference)
#include <cuda_runtime.h>

#define NN     4096
#define IND    512
#define HIDD   256
#define NHEAD  2
#define OUTD   40
#define LN_EPS 1e-5f
#define KSPLIT 4

// Scratch (static device allocations — allowed; no runtime alloc).
__device__ float g_QKV[3][NHEAD][NN][HIDD];        // 24 MB: Q,K,V
__device__ float g_S[NHEAD][NN][NN];               // 134 MB: scores -> probs (in place)
__device__ float g_Xpart[KSPLIT][NN][NHEAD*HIDD];  // 32 MB: split-K partials of attn out
__device__ float g_Xf[NN][NHEAD * HIDD];           // 8 MB: concat attention output
__device__ float g_z[NN][IND];                     // 8 MB: pre-LN activations

#define BM 128
#define BN 128
#define BK 16

// ---------------------------------------------------------------------------
// Double-buffered 128x128x16 fp32 GEMM bodies.
// A is staged k-major (transposed store), B n-major unless noted.
// ---------------------------------------------------------------------------

// A loader: rows m-major with leading dim lda -> regs
#define LOAD_A(ra, Aptr, lda, k0)                                            \
    {                                                                        \
        _Pragma("unroll")                                                    \
        for (int l = 0; l < 2; l++) {                                        \
            int lin = tid + l * 256;                                         \
            int row = lin >> 2, kv = (lin & 3) * 4;                          \
            ra[l] = *(const float4*)&(Aptr)[(size_t)(m0 + row) * (lda) + (k0) + kv]; \
        }                                                                    \
    }

#define STORE_A(ra, Abuf)                                                    \
    {                                                                        \
        _Pragma("unroll")                                                    \
        for (int l = 0; l < 2; l++) {                                        \
            int lin = tid + l * 256;                                         \
            int row = lin >> 2, kv = (lin & 3) * 4;                          \
            Abuf[kv + 0][row] = ra[l].x; Abuf[kv + 1][row] = ra[l].y;        \
            Abuf[kv + 2][row] = ra[l].z; Abuf[kv + 3][row] = ra[l].w;        \
        }                                                                    \
    }

// B loader: n-major, leading dim ldb
#define LOAD_B(rb, Bptr, ldb, k0)                                            \
    {                                                                        \
        _Pragma("unroll")                                                    \
        for (int l = 0; l < 2; l++) {                                        \
            int lin = tid + l * 256;                                         \
            int kr = lin >> 5, nv = (lin & 31) * 4;                          \
            rb[l] = *(const float4*)&(Bptr)[(size_t)((k0) + kr) * (ldb) + n0 + nv]; \
        }                                                                    \
    }

#define STORE_B(rb, Bbuf)                                                    \
    {                                                                        \
        _Pragma("unroll")                                                    \
        for (int l = 0; l < 2; l++) {                                        \
            int lin = tid + l * 256;                                         \
            int kr = lin >> 5, nv = (lin & 31) * 4;                          \
            *(float4*)&Bbuf[kr][nv] = rb[l];                                 \
        }                                                                    \
    }

// B loader for NT (B rows are n-major over n, k contiguous like A)
#define LOAD_BT(rb, Bptr, ldb, k0)                                           \
    {                                                                        \
        _Pragma("unroll")                                                    \
        for (int l = 0; l < 2; l++) {                                        \
            int lin = tid + l * 256;                                         \
            int row = lin >> 2, kv = (lin & 3) * 4;                          \
            rb[l] = *(const float4*)&(Bptr)[(size_t)(n0 + row) * (ldb) + (k0) + kv]; \
        }                                                                    \
    }

#define STORE_BT(rb, Bbuf)                                                   \
    {                                                                        \
        _Pragma("unroll")                                                    \
        for (int l = 0; l < 2; l++) {                                        \
            int lin = tid + l * 256;                                         \
            int row = lin >> 2, kv = (lin & 3) * 4;                          \
            Bbuf[kv + 0][row] = rb[l].x; Bbuf[kv + 1][row] = rb[l].y;        \
            Bbuf[kv + 2][row] = rb[l].z; Bbuf[kv + 3][row] = rb[l].w;        \
        }                                                                    \
    }

#define COMPUTE_TILE(Abuf, Bbuf)                                             \
    {                                                                        \
        _Pragma("unroll")                                                    \
        for (int kk = 0; kk < BK; kk++) {                                    \
            float a[8], b[8];                                                \
            *(float4*)&a[0] = *(float4*)&Abuf[kk][ty * 8];                   \
            *(float4*)&a[4] = *(float4*)&Abuf[kk][ty * 8 + 4];               \
            *(float4*)&b[0] = *(float4*)&Bbuf[kk][tx * 8];                   \
            *(float4*)&b[4] = *(float4*)&Bbuf[kk][tx * 8 + 4];               \
            _Pragma("unroll")                                                \
            for (int i = 0; i < 8; i++)                                      \
                _Pragma("unroll")                                            \
                for (int j = 0; j < 8; j++)                                  \
                    acc[i][j] += a[i] * b[j];                                \
        }                                                                    \
    }

// ---------------------------------------------------------------------------
// Kernel 1: Q/K/V projections. grid: (2, 32, 6)
// ---------------------------------------------------------------------------
__global__ __launch_bounds__(256) void qkv_kernel(
    const float* __restrict__ h,
    const float* __restrict__ Wq, const float* __restrict__ bq,
    const float* __restrict__ Wk, const float* __restrict__ bk,
    const float* __restrict__ Wv, const float* __restrict__ bv)
{
    __shared__ float As[2][BK][BM];
    __shared__ float Bs[2][BK][BN];

    const int mat  = blockIdx.z >> 1;
    const int head = blockIdx.z & 1;
    const float* W    = (mat == 0 ? Wq : (mat == 1 ? Wk : Wv)) + head * IND * HIDD;
    const float* bias = (mat == 0 ? bq : (mat == 1 ? bk : bv)) + head * HIDD;

    const int m0 = blockIdx.y * BM;
    const int n0 = blockIdx.x * BN;
    const int tid = threadIdx.x;
    const int tx = tid & 15, ty = tid >> 4;

    float acc[8][8] = {};
    float4 ra[2], rb[2];

    LOAD_A(ra, h, IND, 0)
    LOAD_B(rb, W, HIDD, 0)
    STORE_A(ra, As[0])
    STORE_B(rb, Bs[0])
    __syncthreads();

    const int T = IND / BK;
    for (int t = 0; t < T; t++) {
        int cur = t & 1;
        if (t + 1 < T) {
            LOAD_A(ra, h, IND, (t + 1) * BK)
            LOAD_B(rb, W, HIDD, (t + 1) * BK)
        }
        COMPUTE_TILE(As[cur], Bs[cur])
        if (t + 1 < T) {
            STORE_A(ra, As[cur ^ 1])
            STORE_B(rb, Bs[cur ^ 1])
        }
        __syncthreads();
    }

    float* C = &g_QKV[mat][head][0][0];
    #pragma unroll
    for (int i = 0; i < 8; i++) {
        int row = m0 + ty * 8 + i;
        #pragma unroll
        for (int j = 0; j < 8; j++) {
            int col = n0 + tx * 8 + j;
            C[row * HIDD + col] = acc[i][j] + bias[col];
        }
    }
}

// ---------------------------------------------------------------------------
// Kernel 2: scores = (Q @ K^T) * adj. grid: (32, 32, 2)
// ---------------------------------------------------------------------------
__global__ __launch_bounds__(256) void scores_kernel(const float* __restrict__ adj)
{
    __shared__ float As[2][BK][BM];
    __shared__ float Bs[2][BK][BN];

    const int head = blockIdx.z;
    const float* Q  = &g_QKV[0][head][0][0];
    const float* Km = &g_QKV[1][head][0][0];
    const int m0 = blockIdx.y * BM;
    const int n0 = blockIdx.x * BN;
    const int tid = threadIdx.x;
    const int tx = tid & 15, ty = tid >> 4;

    float acc[8][8] = {};
    float4 ra[2], rb[2];

    LOAD_A(ra, Q, HIDD, 0)
    LOAD_BT(rb, Km, HIDD, 0)
    STORE_A(ra, As[0])
    STORE_BT(rb, Bs[0])
    __syncthreads();

    const int T = HIDD / BK;
    for (int t = 0; t < T; t++) {
        int cur = t & 1;
        if (t + 1 < T) {
            LOAD_A(ra, Q, HIDD, (t + 1) * BK)
            LOAD_BT(rb, Km, HIDD, (t + 1) * BK)
        }
        COMPUTE_TILE(As[cur], Bs[cur])
        if (t + 1 < T) {
            STORE_A(ra, As[cur ^ 1])
            STORE_BT(rb, Bs[cur ^ 1])
        }
        __syncthreads();
    }

    #pragma unroll
    for (int i = 0; i < 8; i++) {
        int row = m0 + ty * 8 + i;
        const float* arow = adj + ((size_t)head * NN + row) * NN;
        float* srow = &g_S[head][row][0];
        #pragma unroll
        for (int jv = 0; jv < 2; jv++) {
            int col = n0 + tx * 8 + jv * 4;
            float4 av = *(const float4*)&arow[col];
            float4 s;
            s.x = acc[i][jv * 4 + 0] * av.x;
            s.y = acc[i][jv * 4 + 1] * av.y;
            s.z = acc[i][jv * 4 + 2] * av.z;
            s.w = acc[i][jv * 4 + 3] * av.w;
            *(float4*)&srow[col] = s;
        }
    }
}

// ---------------------------------------------------------------------------
// Kernel 3: row softmax in place on g_S. grid: (4096, 2)
// ---------------------------------------------------------------------------
__global__ __launch_bounds__(256) void softmax_kernel()
{
    __shared__ float rowbuf[NN];
    __shared__ float red[256];

    const int head = blockIdx.y;
    const int row  = blockIdx.x;
    float* S = &g_S[head][row][0];
    const int tid = threadIdx.x;

    float4* rb4 = (float4*)rowbuf;
    float4* s4  = (float4*)S;

    float lmax = -1e30f;
    for (int j = tid; j < NN / 4; j += 256) {
        float4 v = s4[j];
        rb4[j] = v;
        lmax = fmaxf(fmaxf(lmax, v.x), fmaxf(v.y, fmaxf(v.z, v.w)));
    }
    red[tid] = lmax;
    __syncthreads();
    for (int s = 128; s > 0; s >>= 1) {
        if (tid < s) red[tid] = fmaxf(red[tid], red[tid + s]);
        __syncthreads();
    }
    const float mx = red[0];
    __syncthreads();

    float lsum = 0.f;
    for (int j = tid; j < NN / 4; j += 256) {
        float4 v = rb4[j];
        v.x = __expf(v.x - mx); v.y = __expf(v.y - mx);
        v.z = __expf(v.z - mx); v.w = __expf(v.w - mx);
        rb4[j] = v;
        lsum += (v.x + v.y) + (v.z + v.w);
    }
    red[tid] = lsum;
    __syncthreads();
    for (int s = 128; s > 0; s >>= 1) {
        if (tid < s) red[tid] += red[tid + s];
        __syncthreads();
    }
    const float inv = 1.0f / red[0];

    for (int j = tid; j < NN / 4; j += 256) {
        float4 v = rb4[j];
        v.x *= inv; v.y *= inv; v.z *= inv; v.w *= inv;
        s4[j] = v;
    }
}

// ---------------------------------------------------------------------------
// Kernel 4: X_part = P_chunk @ V_chunk (split-K). grid: (2, 32, 2*KSPLIT)
// ---------------------------------------------------------------------------
__global__ __launch_bounds__(256) void attnv_kernel()
{
    __shared__ float As[2][BK][BM];
    __shared__ float Bs[2][BK][BN];

    const int head  = blockIdx.z >> 2;
    const int split = blockIdx.z & 3;
    const float* P = &g_S[head][0][0];
    const float* V = &g_QKV[2][head][0][0];
    const int m0 = blockIdx.y * BM;
    const int n0 = blockIdx.x * BN;
    const int tid = threadIdx.x;
    const int tx = tid & 15, ty = tid >> 4;

    const int kbase = split * (NN / KSPLIT);

    float acc[8][8] = {};
    float4 ra[2], rb[2];

    LOAD_A(ra, P, NN, kbase)
    LOAD_B(rb, V, HIDD, kbase)
    STORE_A(ra, As[0])
    STORE_B(rb, Bs[0])
    __syncthreads();

    const int T = (NN / KSPLIT) / BK;  // 64
    for (int t = 0; t < T; t++) {
        int cur = t & 1;
        if (t + 1 < T) {
            LOAD_A(ra, P, NN, kbase + (t + 1) * BK)
            LOAD_B(rb, V, HIDD, kbase + (t + 1) * BK)
        }
        COMPUTE_TILE(As[cur], Bs[cur])
        if (t + 1 < T) {
            STORE_A(ra, As[cur ^ 1])
            STORE_B(rb, Bs[cur ^ 1])
        }
        __syncthreads();
    }

    #pragma unroll
    for (int i = 0; i < 8; i++) {
        int row = m0 + ty * 8 + i;
        #pragma unroll
        for (int j = 0; j < 8; j++) {
            int col = n0 + tx * 8 + j;
            g_Xpart[split][row][head * HIDD + col] = acc[i][j];
        }
    }
}

// ---------------------------------------------------------------------------
// Kernel 4b: reduce split-K partials. grid: 2048, 256 thr (float4)
// ---------------------------------------------------------------------------
__global__ __launch_bounds__(256) void xreduce_kernel()
{
    int idx = blockIdx.x * 256 + threadIdx.x;   // float4 index
    const float4* p0 = (const float4*)&g_Xpart[0][0][0];
    const float4* p1 = (const float4*)&g_Xpart[1][0][0];
    const float4* p2 = (const float4*)&g_Xpart[2][0][0];
    const float4* p3 = (const float4*)&g_Xpart[3][0][0];
    float4 a = p0[idx], b = p1[idx], c = p2[idx], d = p3[idx];
    float4 r;
    r.x = (a.x + b.x) + (c.x + d.x);
    r.y = (a.y + b.y) + (c.y + d.y);
    r.z = (a.z + b.z) + (c.z + d.z);
    r.w = (a.w + b.w) + (c.w + d.w);
    ((float4*)&g_Xf[0][0])[idx] = r;
}

// ---------------------------------------------------------------------------
// Kernel 5: z = Xf @ Wo + bo. grid: (4, 32)
// ---------------------------------------------------------------------------
__global__ __launch_bounds__(256) void z_kernel(
    const float* __restrict__ Wo, const float* __restrict__ bo)
{
    __shared__ float As[2][BK][BM];
    __shared__ float Bs[2][BK][BN];

    const int m0 = blockIdx.y * BM;
    const int n0 = blockIdx.x * BN;
    const int tid = threadIdx.x;
    const int tx = tid & 15, ty = tid >> 4;
    const float* A = &g_Xf[0][0];

    float acc[8][8] = {};
    float4 ra[2], rb[2];

    LOAD_A(ra, A, IND, 0)
    LOAD_B(rb, Wo, IND, 0)
    STORE_A(ra, As[0])
    STORE_B(rb, Bs[0])
    __syncthreads();

    const int T = IND / BK;
    for (int t = 0; t < T; t++) {
        int cur = t & 1;
        if (t + 1 < T) {
            LOAD_A(ra, A, IND, (t + 1) * BK)
            LOAD_B(rb, Wo, IND, (t + 1) * BK)
        }
        COMPUTE_TILE(As[cur], Bs[cur])
        if (t + 1 < T) {
            STORE_A(ra, As[cur ^ 1])
            STORE_B(rb, Bs[cur ^ 1])
        }
        __syncthreads();
    }

    #pragma unroll
    for (int i = 0; i < 8; i++) {
        int row = m0 + ty * 8 + i;
        #pragma unroll
        for (int j = 0; j < 8; j++) {
            int col = n0 + tx * 8 + j;
            g_z[row][col] = acc[i][j] + bo[col];
        }
    }
}

// ---------------------------------------------------------------------------
// Kernel 6: per-row LayerNorm -> M @ Wp + bp -> softmax(40). grid: 4096
// ---------------------------------------------------------------------------
__global__ __launch_bounds__(128) void lnproj_kernel(
    const float* __restrict__ gamma, const float* __restrict__ beta,
    const float* __restrict__ Wp, const float* __restrict__ bp,
    float* __restrict__ out)
{
    __shared__ float Ms[IND];
    __shared__ float red[128];
    __shared__ float lg[OUTD];

    const int row = blockIdx.x;
    const int tid = threadIdx.x;
    const float* z = &g_z[row][0];

    float s = 0.f, ss = 0.f;
    for (int j = tid; j < IND; j += 128) {
        float x = z[j];
        Ms[j] = x;
        s += x;
        ss += x * x;
    }
    red[tid] = s;
    __syncthreads();
    for (int k = 64; k > 0; k >>= 1) {
        if (tid < k) red[tid] += red[tid + k];
        __syncthreads();
    }
    const float mu = red[0] * (1.0f / IND);
    __syncthreads();
    red[tid] = ss;
    __syncthreads();
    for (int k = 64; k > 0; k >>= 1) {
        if (tid < k) red[tid] += red[tid + k];
        __syncthreads();
    }
    const float var  = red[0] * (1.0f / IND) - mu * mu;
    const float rstd = rsqrtf(var + LN_EPS);

    for (int j = tid; j < IND; j += 128)
        Ms[j] = (Ms[j] - mu) * rstd * gamma[j] + beta[j];
    __syncthreads();

    if (tid < OUTD) {
        float acc = bp[tid];
        #pragma unroll 8
        for (int j = 0; j < IND; j++)
            acc += Ms[j] * Wp[j * OUTD + tid];
        lg[tid] = acc;
    }
    __syncthreads();

    if (tid < OUTD) {
        float mx = -1e30f;
        #pragma unroll
        for (int o = 0; o < OUTD; o++) mx = fmaxf(mx, lg[o]);
        float sum = 0.f;
        #pragma unroll
        for (int o = 0; o < OUTD; o++) sum += __expf(lg[o] - mx);
        out[row * OUTD + tid] = __expf(lg[tid] - mx) / sum;
    }
}

// ---------------------------------------------------------------------------
extern "C" void kernel_launch(void* const* d_in, const int* in_sizes, int n_in,
                              void* d_out, int out_size)
{
    const float* adj   = (const float*)d_in[0];
    const float* h     = (const float*)d_in[1];
    const float* Wq    = (const float*)d_in[2];
    const float* bq    = (const float*)d_in[3];
    const float* Wk    = (const float*)d_in[4];
    const float* bk    = (const float*)d_in[5];
    const float* Wv    = (const float*)d_in[6];
    const float* bv    = (const float*)d_in[7];
    const float* Wo    = (const float*)d_in[8];
    const float* bo    = (const float*)d_in[9];
    const float* gamma = (const float*)d_in[10];
    const float* beta  = (const float*)d_in[11];
    const float* Wp    = (const float*)d_in[12];
    const float* bp    = (const float*)d_in[13];
    float* out = (float*)d_out;

    qkv_kernel<<<dim3(HIDD / BN, NN / BM, 6), 256>>>(h, Wq, bq, Wk, bk, Wv, bv);
    scores_kernel<<<dim3(NN / BN, NN / BM, NHEAD), 256>>>(adj);
    softmax_kernel<<<dim3(NN, NHEAD), 256>>>();
    attnv_kernel<<<dim3(HIDD / BN, NN / BM, NHEAD * KSPLIT), 256>>>();
    xreduce_kernel<<<(NN * NHEAD * HIDD / 4) / 256, 256>>>();
    z_kernel<<<dim3(IND / BN, NN / BM), 256>>>(Wo, bo);
    lnproj_kernel<<<NN, 128>>>(gamma, beta, Wp, bp, out);
}

// round 4
// speedup vs baseline: 1.8001x; 1.8001x over previous
#include <cuda_runtime.h>
#include <cstdint>

#define NN     4096
#define IND    512
#define HIDD   256
#define NHEAD  2
#define OUTD   40
#define LN_EPS 1e-5f

// Scratch (static device allocations — allowed; no runtime alloc).
__device__ float g_QKV[3][NHEAD][NN][HIDD];   // 24 MB: Q,K,V
__device__ float g_VT[NHEAD][HIDD][NN];       // 8 MB: V transposed [n][k]
__device__ float g_S[NHEAD][NN][NN];          // 134 MB: scores -> probs (in place)
__device__ float g_Xf[NN][NHEAD * HIDD];      // 8 MB: concat attention output
__device__ float g_z[NN][IND];                // 8 MB: pre-LN activations

// ===========================================================================
// Tensor-core (mma.sync, base ISA — no sm_103a-only features) machinery
// ===========================================================================
__device__ __forceinline__ uint32_t smem_to_u32(const void* p) {
    uint32_t a;
    asm("{ .reg .u64 t; cvta.to.shared.u64 t, %1; cvt.u32.u64 %0, t; }" : "=r"(a) : "l"(p));
    return a;
}

__device__ __forceinline__ void ldm4(uint32_t* r, uint32_t addr) {
    asm volatile("ldmatrix.sync.aligned.m8n8.x4.shared.b16 {%0,%1,%2,%3}, [%4];"
                 : "=r"(r[0]), "=r"(r[1]), "=r"(r[2]), "=r"(r[3]) : "r"(addr));
}

__device__ __forceinline__ void mma_bf16(float* d, const uint32_t* a, uint32_t b0, uint32_t b1) {
    asm volatile("mma.sync.aligned.m16n8k16.row.col.f32.bf16.bf16.f32 "
                 "{%0,%1,%2,%3}, {%4,%5,%6,%7}, {%8,%9}, {%0,%1,%2,%3};"
                 : "+f"(d[0]), "+f"(d[1]), "+f"(d[2]), "+f"(d[3])
                 : "r"(a[0]), "r"(a[1]), "r"(a[2]), "r"(a[3]), "r"(b0), "r"(b1));
}

// fp32x4 -> bf16 hi (packed x2,x2) + bf16 lo residual
__device__ __forceinline__ void cvt_hilo(float4 v, uint2& hi, uint2& lo) {
    uint32_t h01, h23;
    asm("cvt.rn.bf16x2.f32 %0, %1, %2;" : "=r"(h01) : "f"(v.y), "f"(v.x));
    asm("cvt.rn.bf16x2.f32 %0, %1, %2;" : "=r"(h23) : "f"(v.w), "f"(v.z));
    float hx = __uint_as_float(h01 << 16);
    float hy = __uint_as_float(h01 & 0xFFFF0000u);
    float hz = __uint_as_float(h23 << 16);
    float hw = __uint_as_float(h23 & 0xFFFF0000u);
    float lx = v.x - hx, ly = v.y - hy, lz = v.z - hz, lw = v.w - hw;
    uint32_t l01, l23;
    asm("cvt.rn.bf16x2.f32 %0, %1, %2;" : "=r"(l01) : "f"(ly), "f"(lx));
    asm("cvt.rn.bf16x2.f32 %0, %1, %2;" : "=r"(l23) : "f"(lw), "f"(lz));
    hi.x = h01; hi.y = h23;
    lo.x = l01; lo.y = l23;
}

// smem tile: 128 rows x 32 k of bf16, row stride 80 B (odd multiple of 16B =>
// ldmatrix 8-row phases hit distinct 16B chunks mod 128B: conflict-free).
#define RS      80
#define TILE_B  (128 * RS)          // 10240 B
#define STG_B   (4 * TILE_B)        // A_hi, A_lo, B_hi, B_lo
#define TC_SMEM (2 * STG_B)         // 81920 B, double buffered

// D[128x128] += A[128xK] (row-major, lda) * B[128xK]^T (row-major n-major, ldb)
// 8 warps: wm = wid>>2 (2), wn = wid&3 (4); warp tile 64x32.
__device__ __forceinline__ void tc_mainloop(
    const float* __restrict__ A, int lda, int m0,
    const float* __restrict__ B, int ldb, int n0,
    int Kdim, char* smem, float acc[4][4][4])
{
    const int tid  = threadIdx.x;
    const int lane = tid & 31, wid = tid >> 5;
    const int wm = wid >> 2, wn = wid & 3;
    const uint32_t sb = smem_to_u32(smem);

    float4 ra[4], rb[4];

    // loader mapping: lin = tid + i*256 ; row = lin>>3 ; kgroup = lin&7 (float4)
    #define TC_LOAD(reg, P, ld, r0, kc)                                          \
        { _Pragma("unroll")                                                      \
          for (int i = 0; i < 4; i++) {                                          \
              int lin = tid + i * 256; int r = lin >> 3, kg = lin & 7;           \
              reg[i] = *(const float4*)&(P)[(size_t)((r0) + r) * (ld) + (kc) + kg * 4]; } }

    #define TC_STORE(reg, off_hi)                                                \
        { _Pragma("unroll")                                                      \
          for (int i = 0; i < 4; i++) {                                          \
              int lin = tid + i * 256; int r = lin >> 3, kg = lin & 7;           \
              uint2 hi, lo; cvt_hilo(reg[i], hi, lo);                            \
              *(uint2*)(smem + (off_hi) + r * RS + kg * 8) = hi;                 \
              *(uint2*)(smem + (off_hi) + TILE_B + r * RS + kg * 8) = lo; } }

    TC_LOAD(ra, A, lda, m0, 0)
    TC_LOAD(rb, B, ldb, n0, 0)
    TC_STORE(ra, 0)
    TC_STORE(rb, 2 * TILE_B)
    __syncthreads();

    const int T = Kdim / 32;
    for (int t = 0; t < T; t++) {
        const uint32_t stg  = (uint32_t)(t & 1) * STG_B;
        const uint32_t nstg = stg ^ STG_B;

        if (t + 1 < T) {
            TC_LOAD(ra, A, lda, m0, (t + 1) * 32)
            TC_LOAD(rb, B, ldb, n0, (t + 1) * 32)
        }

        #pragma unroll
        for (int ks = 0; ks < 2; ks++) {
            uint32_t aH[4][4], aL[4][4], bH[2][4], bL[2][4];
            const int mat   = lane >> 3;
            const int chunk = ks * 2 + (mat >> 1);
            #pragma unroll
            for (int mf = 0; mf < 4; mf++) {
                int row = wm * 64 + mf * 16 + ((mat & 1) << 3) + (lane & 7);
                uint32_t ad = sb + stg + row * RS + chunk * 16;
                ldm4(aH[mf], ad);
                ldm4(aL[mf], ad + TILE_B);
            }
            #pragma unroll
            for (int p = 0; p < 2; p++) {
                int row = wn * 32 + p * 16 + ((mat & 1) << 3) + (lane & 7);
                uint32_t ad = sb + stg + 2 * TILE_B + row * RS + chunk * 16;
                ldm4(bH[p], ad);
                ldm4(bL[p], ad + TILE_B);
            }
            #pragma unroll
            for (int mf = 0; mf < 4; mf++)
                #pragma unroll
                for (int nf = 0; nf < 4; nf++) {
                    int p = nf >> 1, q = nf & 1;
                    mma_bf16(acc[mf][nf], aH[mf], bH[p][q], bH[p][q + 2]);
                    mma_bf16(acc[mf][nf], aH[mf], bL[p][q], bL[p][q + 2]);
                    mma_bf16(acc[mf][nf], aL[mf], bH[p][q], bH[p][q + 2]);
                }
        }

        if (t + 1 < T) {
            TC_STORE(ra, nstg)
            TC_STORE(rb, nstg + 2 * TILE_B)
        }
        __syncthreads();
    }
    #undef TC_LOAD
    #undef TC_STORE
}

// ---------------------------------------------------------------------------
// tc scores: S = (Q @ K^T) * adj.  grid (32, 32, 2), 256 thr, 80KB dyn smem.
// ---------------------------------------------------------------------------
__global__ __launch_bounds__(256, 1) void tc_scores_kernel(const float* __restrict__ adj)
{
    extern __shared__ char smem[];
    const int head = blockIdx.z;
    const int m0 = blockIdx.y * 128;
    const int n0 = blockIdx.x * 128;

    float acc[4][4][4] = {};
    tc_mainloop(&g_QKV[0][head][0][0], HIDD, m0,
                &g_QKV[1][head][0][0], HIDD, n0, HIDD, smem, acc);

    const int lane = threadIdx.x & 31, wid = threadIdx.x >> 5;
    const int wm = wid >> 2, wn = wid & 3;
    const int rbase = m0 + wm * 64 + (lane >> 2);
    const int cbase = n0 + wn * 32 + (lane & 3) * 2;

    #pragma unroll
    for (int mf = 0; mf < 4; mf++)
        #pragma unroll
        for (int nf = 0; nf < 4; nf++) {
            int c = cbase + nf * 8;
            #pragma unroll
            for (int hh = 0; hh < 2; hh++) {
                int r = rbase + mf * 16 + hh * 8;
                float2 av = *(const float2*)&adj[((size_t)head * NN + r) * NN + c];
                float2 s;
                s.x = acc[mf][nf][2 * hh + 0] * av.x;
                s.y = acc[mf][nf][2 * hh + 1] * av.y;
                *(float2*)&g_S[head][r][c] = s;
            }
        }
}

// ---------------------------------------------------------------------------
// tc attnv: Xf = P @ V (via VT).  grid (2, 32, 2), 256 thr, 80KB dyn smem.
// ---------------------------------------------------------------------------
__global__ __launch_bounds__(256, 1) void tc_attnv_kernel()
{
    extern __shared__ char smem[];
    const int head = blockIdx.z;
    const int m0 = blockIdx.y * 128;
    const int n0 = blockIdx.x * 128;

    float acc[4][4][4] = {};
    tc_mainloop(&g_S[head][0][0], NN, m0,
                &g_VT[head][0][0], NN, n0, NN, smem, acc);

    const int lane = threadIdx.x & 31, wid = threadIdx.x >> 5;
    const int wm = wid >> 2, wn = wid & 3;
    const int rbase = m0 + wm * 64 + (lane >> 2);
    const int cbase = n0 + wn * 32 + (lane & 3) * 2;

    #pragma unroll
    for (int mf = 0; mf < 4; mf++)
        #pragma unroll
        for (int nf = 0; nf < 4; nf++) {
            int c = cbase + nf * 8;
            #pragma unroll
            for (int hh = 0; hh < 2; hh++) {
                int r = rbase + mf * 16 + hh * 8;
                float2 s;
                s.x = acc[mf][nf][2 * hh + 0];
                s.y = acc[mf][nf][2 * hh + 1];
                *(float2*)&g_Xf[r][head * HIDD + c] = s;
            }
        }
}

// ---------------------------------------------------------------------------
// V transpose: g_QKV[2][h][k][n] -> g_VT[h][n][k].  grid (128, 8, 2), block (32,8)
// ---------------------------------------------------------------------------
__global__ __launch_bounds__(256) void vtrans_kernel()
{
    __shared__ float tile[32][33];
    const int h = blockIdx.z;
    const int k0 = blockIdx.x * 32, n0 = blockIdx.y * 32;
    const int tx = threadIdx.x, ty = threadIdx.y;
    #pragma unroll
    for (int i = 0; i < 32; i += 8)
        tile[ty + i][tx] = g_QKV[2][h][k0 + ty + i][n0 + tx];
    __syncthreads();
    #pragma unroll
    for (int i = 0; i < 32; i += 8)
        g_VT[h][n0 + ty + i][k0 + tx] = tile[tx][ty + i];
}

// ===========================================================================
// SIMT fp32 GEMM machinery (qkv, z)
// ===========================================================================
#define BM 128
#define BN 128
#define BK 16

#define LOAD_A(ra, Aptr, lda, k0)                                            \
    {                                                                        \
        _Pragma("unroll")                                                    \
        for (int l = 0; l < 2; l++) {                                        \
            int lin = tid + l * 256;                                         \
            int row = lin >> 2, kv = (lin & 3) * 4;                          \
            ra[l] = *(const float4*)&(Aptr)[(size_t)(m0 + row) * (lda) + (k0) + kv]; \
        }                                                                    \
    }
#define STORE_A(ra, Abuf)                                                    \
    {                                                                        \
        _Pragma("unroll")                                                    \
        for (int l = 0; l < 2; l++) {                                        \
            int lin = tid + l * 256;                                         \
            int row = lin >> 2, kv = (lin & 3) * 4;                          \
            Abuf[kv + 0][row] = ra[l].x; Abuf[kv + 1][row] = ra[l].y;        \
            Abuf[kv + 2][row] = ra[l].z; Abuf[kv + 3][row] = ra[l].w;        \
        }                                                                    \
    }
#define LOAD_B(rb, Bptr, ldb, k0)                                            \
    {                                                                        \
        _Pragma("unroll")                                                    \
        for (int l = 0; l < 2; l++) {                                        \
            int lin = tid + l * 256;                                         \
            int kr = lin >> 5, nv = (lin & 31) * 4;                          \
            rb[l] = *(const float4*)&(Bptr)[(size_t)((k0) + kr) * (ldb) + n0 + nv]; \
        }                                                                    \
    }
#define STORE_B(rb, Bbuf)                                                    \
    {                                                                        \
        _Pragma("unroll")                                                    \
        for (int l = 0; l < 2; l++) {                                        \
            int lin = tid + l * 256;                                         \
            int kr = lin >> 5, nv = (lin & 31) * 4;                          \
            *(float4*)&Bbuf[kr][nv] = rb[l];                                 \
        }                                                                    \
    }
#define COMPUTE_TILE(Abuf, Bbuf)                                             \
    {                                                                        \
        _Pragma("unroll")                                                    \
        for (int kk = 0; kk < BK; kk++) {                                    \
            float a[8], b[8];                                                \
            *(float4*)&a[0] = *(float4*)&Abuf[kk][ty * 8];                   \
            *(float4*)&a[4] = *(float4*)&Abuf[kk][ty * 8 + 4];               \
            *(float4*)&b[0] = *(float4*)&Bbuf[kk][tx * 8];                   \
            *(float4*)&b[4] = *(float4*)&Bbuf[kk][tx * 8 + 4];               \
            _Pragma("unroll")                                                \
            for (int i = 0; i < 8; i++)                                      \
                _Pragma("unroll")                                            \
                for (int j = 0; j < 8; j++)                                  \
                    acc[i][j] += a[i] * b[j];                                \
        }                                                                    \
    }

__global__ __launch_bounds__(256) void qkv_kernel(
    const float* __restrict__ h,
    const float* __restrict__ Wq, const float* __restrict__ bq,
    const float* __restrict__ Wk, const float* __restrict__ bk,
    const float* __restrict__ Wv, const float* __restrict__ bv)
{
    __shared__ float As[2][BK][BM];
    __shared__ float Bs[2][BK][BN];

    const int mat  = blockIdx.z >> 1;
    const int head = blockIdx.z & 1;
    const float* W    = (mat == 0 ? Wq : (mat == 1 ? Wk : Wv)) + head * IND * HIDD;
    const float* bias = (mat == 0 ? bq : (mat == 1 ? bk : bv)) + head * HIDD;

    const int m0 = blockIdx.y * BM;
    const int n0 = blockIdx.x * BN;
    const int tid = threadIdx.x;
    const int tx = tid & 15, ty = tid >> 4;

    float acc[8][8] = {};
    float4 ra[2], rb[2];

    LOAD_A(ra, h, IND, 0)
    LOAD_B(rb, W, HIDD, 0)
    STORE_A(ra, As[0])
    STORE_B(rb, Bs[0])
    __syncthreads();

    const int T = IND / BK;
    for (int t = 0; t < T; t++) {
        int cur = t & 1;
        if (t + 1 < T) {
            LOAD_A(ra, h, IND, (t + 1) * BK)
            LOAD_B(rb, W, HIDD, (t + 1) * BK)
        }
        COMPUTE_TILE(As[cur], Bs[cur])
        if (t + 1 < T) {
            STORE_A(ra, As[cur ^ 1])
            STORE_B(rb, Bs[cur ^ 1])
        }
        __syncthreads();
    }

    float* C = &g_QKV[mat][head][0][0];
    #pragma unroll
    for (int i = 0; i < 8; i++) {
        int row = m0 + ty * 8 + i;
        #pragma unroll
        for (int j = 0; j < 8; j++) {
            int col = n0 + tx * 8 + j;
            C[row * HIDD + col] = acc[i][j] + bias[col];
        }
    }
}

__global__ __launch_bounds__(256) void z_kernel(
    const float* __restrict__ Wo, const float* __restrict__ bo)
{
    __shared__ float As[2][BK][BM];
    __shared__ float Bs[2][BK][BN];

    const int m0 = blockIdx.y * BM;
    const int n0 = blockIdx.x * BN;
    const int tid = threadIdx.x;
    const int tx = tid & 15, ty = tid >> 4;
    const float* A = &g_Xf[0][0];

    float acc[8][8] = {};
    float4 ra[2], rb[2];

    LOAD_A(ra, A, IND, 0)
    LOAD_B(rb, Wo, IND, 0)
    STORE_A(ra, As[0])
    STORE_B(rb, Bs[0])
    __syncthreads();

    const int T = IND / BK;
    for (int t = 0; t < T; t++) {
        int cur = t & 1;
        if (t + 1 < T) {
            LOAD_A(ra, A, IND, (t + 1) * BK)
            LOAD_B(rb, Wo, IND, (t + 1) * BK)
        }
        COMPUTE_TILE(As[cur], Bs[cur])
        if (t + 1 < T) {
            STORE_A(ra, As[cur ^ 1])
            STORE_B(rb, Bs[cur ^ 1])
        }
        __syncthreads();
    }

    #pragma unroll
    for (int i = 0; i < 8; i++) {
        int row = m0 + ty * 8 + i;
        #pragma unroll
        for (int j = 0; j < 8; j++) {
            int col = n0 + tx * 8 + j;
            g_z[row][col] = acc[i][j] + bo[col];
        }
    }
}

// ---------------------------------------------------------------------------
// Row softmax in place on g_S. grid: (4096, 2)
// ---------------------------------------------------------------------------
__global__ __launch_bounds__(256) void softmax_kernel()
{
    __shared__ float rowbuf[NN];
    __shared__ float red[256];

    const int head = blockIdx.y;
    const int row  = blockIdx.x;
    float* S = &g_S[head][row][0];
    const int tid = threadIdx.x;

    float4* rb4 = (float4*)rowbuf;
    float4* s4  = (float4*)S;

    float lmax = -1e30f;
    for (int j = tid; j < NN / 4; j += 256) {
        float4 v = s4[j];
        rb4[j] = v;
        lmax = fmaxf(fmaxf(lmax, v.x), fmaxf(v.y, fmaxf(v.z, v.w)));
    }
    red[tid] = lmax;
    __syncthreads();
    for (int s = 128; s > 0; s >>= 1) {
        if (tid < s) red[tid] = fmaxf(red[tid], red[tid + s]);
        __syncthreads();
    }
    const float mx = red[0];
    __syncthreads();

    float lsum = 0.f;
    for (int j = tid; j < NN / 4; j += 256) {
        float4 v = rb4[j];
        v.x = __expf(v.x - mx); v.y = __expf(v.y - mx);
        v.z = __expf(v.z - mx); v.w = __expf(v.w - mx);
        rb4[j] = v;
        lsum += (v.x + v.y) + (v.z + v.w);
    }
    red[tid] = lsum;
    __syncthreads();
    for (int s = 128; s > 0; s >>= 1) {
        if (tid < s) red[tid] += red[tid + s];
        __syncthreads();
    }
    const float inv = 1.0f / red[0];

    for (int j = tid; j < NN / 4; j += 256) {
        float4 v = rb4[j];
        v.x *= inv; v.y *= inv; v.z *= inv; v.w *= inv;
        s4[j] = v;
    }
}

// ---------------------------------------------------------------------------
// Per-row LayerNorm -> M @ Wp + bp -> softmax(40). grid: 4096
// ---------------------------------------------------------------------------
__global__ __launch_bounds__(128) void lnproj_kernel(
    const float* __restrict__ gamma, const float* __restrict__ beta,
    const float* __restrict__ Wp, const float* __restrict__ bp,
    float* __restrict__ out)
{
    __shared__ float Ms[IND];
    __shared__ float red[128];
    __shared__ float lg[OUTD];

    const int row = blockIdx.x;
    const int tid = threadIdx.x;
    const float* z = &g_z[row][0];

    float s = 0.f, ss = 0.f;
    for (int j = tid; j < IND; j += 128) {
        float x = z[j];
        Ms[j] = x;
        s += x;
        ss += x * x;
    }
    red[tid] = s;
    __syncthreads();
    for (int k = 64; k > 0; k >>= 1) {
        if (tid < k) red[tid] += red[tid + k];
        __syncthreads();
    }
    const float mu = red[0] * (1.0f / IND);
    __syncthreads();
    red[tid] = ss;
    __syncthreads();
    for (int k = 64; k > 0; k >>= 1) {
        if (tid < k) red[tid] += red[tid + k];
        __syncthreads();
    }
    const float var  = red[0] * (1.0f / IND) - mu * mu;
    const float rstd = rsqrtf(var + LN_EPS);

    for (int j = tid; j < IND; j += 128)
        Ms[j] = (Ms[j] - mu) * rstd * gamma[j] + beta[j];
    __syncthreads();

    if (tid < OUTD) {
        float acc = bp[tid];
        #pragma unroll 8
        for (int j = 0; j < IND; j++)
            acc += Ms[j] * Wp[j * OUTD + tid];
        lg[tid] = acc;
    }
    __syncthreads();

    if (tid < OUTD) {
        float mx = -1e30f;
        #pragma unroll
        for (int o = 0; o < OUTD; o++) mx = fmaxf(mx, lg[o]);
        float sum = 0.f;
        #pragma unroll
        for (int o = 0; o < OUTD; o++) sum += __expf(lg[o] - mx);
        out[row * OUTD + tid] = __expf(lg[tid] - mx) / sum;
    }
}

// ---------------------------------------------------------------------------
extern "C" void kernel_launch(void* const* d_in, const int* in_sizes, int n_in,
                              void* d_out, int out_size)
{
    const float* adj   = (const float*)d_in[0];
    const float* h     = (const float*)d_in[1];
    const float* Wq    = (const float*)d_in[2];
    const float* bq    = (const float*)d_in[3];
    const float* Wk    = (const float*)d_in[4];
    const float* bk    = (const float*)d_in[5];
    const float* Wv    = (const float*)d_in[6];
    const float* bv    = (const float*)d_in[7];
    const float* Wo    = (const float*)d_in[8];
    const float* bo    = (const float*)d_in[9];
    const float* gamma = (const float*)d_in[10];
    const float* beta  = (const float*)d_in[11];
    const float* Wp    = (const float*)d_in[12];
    const float* bp    = (const float*)d_in[13];
    float* out = (float*)d_out;

    // opt into large dynamic smem (host-side attribute, idempotent, not a graph node)
    cudaFuncSetAttribute(tc_scores_kernel, cudaFuncAttributeMaxDynamicSharedMemorySize, TC_SMEM);
    cudaFuncSetAttribute(tc_attnv_kernel,  cudaFuncAttributeMaxDynamicSharedMemorySize, TC_SMEM);

    qkv_kernel<<<dim3(HIDD / BN, NN / BM, 6), 256>>>(h, Wq, bq, Wk, bk, Wv, bv);
    vtrans_kernel<<<dim3(NN / 32, HIDD / 32, NHEAD), dim3(32, 8)>>>();
    tc_scores_kernel<<<dim3(NN / 128, NN / 128, NHEAD), 256, TC_SMEM>>>(adj);
    softmax_kernel<<<dim3(NN, NHEAD), 256>>>();
    tc_attnv_kernel<<<dim3(HIDD / 128, NN / 128, NHEAD), 256, TC_SMEM>>>();
    z_kernel<<<dim3(IND / BN, NN / BM), 256>>>(Wo, bo);
    lnproj_kernel<<<NN, 128>>>(gamma, beta, Wp, bp, out);
}

// round 6
// speedup vs baseline: 2.0664x; 1.1480x over previous
#include <cuda_runtime.h>
#include <cuda_bf16.h>
#include <cstdint>

#define NN     4096
#define IND    512
#define HIDD   256
#define NHEAD  2
#define OUTD   40
#define LN_EPS 1e-5f

// ---------------------------------------------------------------------------
// Static device scratch (no runtime allocation).
// ---------------------------------------------------------------------------
__device__ float          g_V [NHEAD][NN][HIDD];      // V fp32 (pre-transpose)
__device__ float          g_S [NHEAD][NN][NN];        // scores fp32
__device__ float          g_z [NN][IND];              // pre-LN activations
// bf16 hi/lo operand planes
__device__ __nv_bfloat16  g_hh[NN][IND],        g_hl[NN][IND];
__device__ __nv_bfloat16  g_Qh[NHEAD][NN][HIDD], g_Ql[NHEAD][NN][HIDD];
__device__ __nv_bfloat16  g_Kh[NHEAD][NN][HIDD], g_Kl[NHEAD][NN][HIDD];
__device__ __nv_bfloat16  g_VTh[NHEAD][HIDD][NN], g_VTl[NHEAD][HIDD][NN];
__device__ __nv_bfloat16  g_Ph[NHEAD][NN][NN],   g_Pl[NHEAD][NN][NN];
__device__ __nv_bfloat16  g_Xfh[NN][IND],        g_Xfl[NN][IND];
__device__ __nv_bfloat16  g_WTh[6][HIDD][IND],   g_WTl[6][HIDD][IND];   // qkv weights^T
__device__ __nv_bfloat16  g_WoTh[IND][2*HIDD],   g_WoTl[IND][2*HIDD];   // Wo^T

// ---------------------------------------------------------------------------
// Helpers
// ---------------------------------------------------------------------------
__device__ __forceinline__ uint32_t smem_to_u32(const void* p) {
    uint32_t a;
    asm("{ .reg .u64 t; cvta.to.shared.u64 t, %1; cvt.u32.u64 %0, t; }" : "=r"(a) : "l"(p));
    return a;
}
__device__ __forceinline__ void ldm4(uint32_t* r, uint32_t addr) {
    asm volatile("ldmatrix.sync.aligned.m8n8.x4.shared.b16 {%0,%1,%2,%3}, [%4];"
                 : "=r"(r[0]), "=r"(r[1]), "=r"(r[2]), "=r"(r[3]) : "r"(addr));
}
__device__ __forceinline__ void mma_bf16(float* d, const uint32_t* a, uint32_t b0, uint32_t b1) {
    asm volatile("mma.sync.aligned.m16n8k16.row.col.f32.bf16.bf16.f32 "
                 "{%0,%1,%2,%3}, {%4,%5,%6,%7}, {%8,%9}, {%0,%1,%2,%3};"
                 : "+f"(d[0]), "+f"(d[1]), "+f"(d[2]), "+f"(d[3])
                 : "r"(a[0]), "r"(a[1]), "r"(a[2]), "r"(a[3]), "r"(b0), "r"(b1));
}
__device__ __forceinline__ void cp_async16(uint32_t dst, const void* src) {
    asm volatile("cp.async.cg.shared.global [%0], [%1], 16;" :: "r"(dst), "l"(src));
}
#define CP_COMMIT() asm volatile("cp.async.commit_group;" ::: "memory")
#define CP_WAIT1()  asm volatile("cp.async.wait_group 1;" ::: "memory")

// fp32x4 -> packed bf16x2 hi + lo residual
__device__ __forceinline__ void cvt_hilo(float4 v, uint2& hi, uint2& lo) {
    uint32_t h01, h23;
    asm("cvt.rn.bf16x2.f32 %0, %1, %2;" : "=r"(h01) : "f"(v.y), "f"(v.x));
    asm("cvt.rn.bf16x2.f32 %0, %1, %2;" : "=r"(h23) : "f"(v.w), "f"(v.z));
    float hx = __uint_as_float(h01 << 16);
    float hy = __uint_as_float(h01 & 0xFFFF0000u);
    float hz = __uint_as_float(h23 << 16);
    float hw = __uint_as_float(h23 & 0xFFFF0000u);
    float lx = v.x - hx, ly = v.y - hy, lz = v.z - hz, lw = v.w - hw;
    uint32_t l01, l23;
    asm("cvt.rn.bf16x2.f32 %0, %1, %2;" : "=r"(l01) : "f"(ly), "f"(lx));
    asm("cvt.rn.bf16x2.f32 %0, %1, %2;" : "=r"(l23) : "f"(lw), "f"(lz));
    hi.x = h01; hi.y = h23;
    lo.x = l01; lo.y = l23;
}
__device__ __forceinline__ void split1(float v, __nv_bfloat16& h, __nv_bfloat16& l) {
    h = __float2bfloat16(v);
    l = __float2bfloat16(v - __bfloat162float(h));
}

// ---------------------------------------------------------------------------
// tc GEMM mainloop: acc[128x128] += A[128xK] (row-major k-contig, hi/lo planes)
//                              * B[128xK]^T (row-major k-contig, hi/lo planes)
// cp.async 3-stage pipeline; smem tiles 128 rows x 64B, row stride 80B
// (odd multiple of 16B -> ldmatrix conflict-free).
// 8 warps: wm = wid>>2, wn = wid&3; warp tile 64x32. 3-product bf16 split.
// ---------------------------------------------------------------------------
#define RS      80
#define TILE_B  (128 * RS)          // 10240 B per plane
#define STG_B   (4 * TILE_B)        // Ahi, Alo, Bhi, Blo
#define S_STG   3
#define TC_SMEM (S_STG * STG_B)     // 122880 B

__device__ __forceinline__ void tc_mainloop(
    const __nv_bfloat16* __restrict__ Ah, const __nv_bfloat16* __restrict__ Al,
    int lda, int m0,
    const __nv_bfloat16* __restrict__ Bh, const __nv_bfloat16* __restrict__ Bl,
    int ldb, int n0,
    int Kdim, char* smem, float acc[4][4][4])
{
    const int tid  = threadIdx.x;
    const int lane = tid & 31, wid = tid >> 5;
    const int wm = wid >> 2, wn = wid & 3;
    const uint32_t sb = smem_to_u32(smem);

    // issue one k-chunk (32 k = 64B/row) into stage slot: 2048 x 16B chunks
    #define TC_ISSUE(slot, kc)                                                   \
        { _Pragma("unroll")                                                      \
          for (int i = 0; i < 8; i++) {                                          \
              int lin = tid + i * 256;                                           \
              int plane = lin >> 9;                                              \
              int r = (lin >> 2) & 127;                                          \
              int kg = lin & 3;                                                  \
              const __nv_bfloat16* src;                                          \
              if (plane == 0)      src = &Ah[(size_t)(m0 + r) * lda + (kc) + kg * 8]; \
              else if (plane == 1) src = &Al[(size_t)(m0 + r) * lda + (kc) + kg * 8]; \
              else if (plane == 2) src = &Bh[(size_t)(n0 + r) * ldb + (kc) + kg * 8]; \
              else                 src = &Bl[(size_t)(n0 + r) * ldb + (kc) + kg * 8]; \
              uint32_t dst = sb + (uint32_t)(slot) * STG_B + plane * TILE_B      \
                             + r * RS + kg * 16;                                 \
              cp_async16(dst, src);                                              \
          }                                                                      \
          CP_COMMIT(); }

    const int T = Kdim / 32;
    TC_ISSUE(0, 0)
    TC_ISSUE(1, 32)

    for (int t = 0; t < T; t++) {
        CP_WAIT1();
        __syncthreads();
        if (t + 2 < T) {
            TC_ISSUE((t + 2) % S_STG, (t + 2) * 32)
        } else {
            CP_COMMIT();   // empty group keeps wait_group bookkeeping uniform
        }

        const uint32_t stg = (uint32_t)(t % S_STG) * STG_B;
        #pragma unroll
        for (int ks = 0; ks < 2; ks++) {
            uint32_t aH[4][4], aL[4][4], bH[2][4], bL[2][4];
            const int mat   = lane >> 3;
            const int chunk = ks * 2 + (mat >> 1);
            #pragma unroll
            for (int mf = 0; mf < 4; mf++) {
                int row = wm * 64 + mf * 16 + ((mat & 1) << 3) + (lane & 7);
                uint32_t ad = sb + stg + row * RS + chunk * 16;
                ldm4(aH[mf], ad);
                ldm4(aL[mf], ad + TILE_B);
            }
            #pragma unroll
            for (int p = 0; p < 2; p++) {
                int row = wn * 32 + p * 16 + ((mat & 1) << 3) + (lane & 7);
                uint32_t ad = sb + stg + 2 * TILE_B + row * RS + chunk * 16;
                ldm4(bH[p], ad);
                ldm4(bL[p], ad + TILE_B);
            }
            #pragma unroll
            for (int mf = 0; mf < 4; mf++)
                #pragma unroll
                for (int nf = 0; nf < 4; nf++) {
                    int p = nf >> 1, q = nf & 1;
                    mma_bf16(acc[mf][nf], aH[mf], bH[p][q], bH[p][q + 2]);
                    mma_bf16(acc[mf][nf], aH[mf], bL[p][q], bL[p][q + 2]);
                    mma_bf16(acc[mf][nf], aL[mf], bH[p][q], bH[p][q + 2]);
                }
        }
    }
    #undef TC_ISSUE
}

// Epilogue index helpers: element (mf, nf, e): row = mf*16 + (e>>1)*8 + lane>>2,
// col = nf*8 + (lane&3)*2 + (e&1)   (within the warp's 64x32 tile)

// ---------------------------------------------------------------------------
// tc qkv: {Q,K,V}[head] = h @ W + b.  grid (2, 32, 6)  z = mat*2 + head
// ---------------------------------------------------------------------------
__global__ __launch_bounds__(256, 1) void tc_qkv_kernel(
    const float* __restrict__ bq, const float* __restrict__ bk, const float* __restrict__ bv)
{
    extern __shared__ char smem[];
    const int mat  = blockIdx.z >> 1;
    const int head = blockIdx.z & 1;
    const int m0 = blockIdx.y * 128;
    const int n0 = blockIdx.x * 128;

    float acc[4][4][4] = {};
    tc_mainloop(&g_hh[0][0], &g_hl[0][0], IND, m0,
                &g_WTh[blockIdx.z][0][0], &g_WTl[blockIdx.z][0][0], IND, n0,
                IND, smem, acc);

    const float* bias = (mat == 0 ? bq : (mat == 1 ? bk : bv)) + head * HIDD;
    const int lane = threadIdx.x & 31, wid = threadIdx.x >> 5;
    const int wm = wid >> 2, wn = wid & 3;
    const int rbase = m0 + wm * 64 + (lane >> 2);
    const int cbase = n0 + wn * 32 + (lane & 3) * 2;

    __nv_bfloat16* outh = (mat == 0) ? &g_Qh[head][0][0] : &g_Kh[head][0][0];
    __nv_bfloat16* outl = (mat == 0) ? &g_Ql[head][0][0] : &g_Kl[head][0][0];

    #pragma unroll
    for (int mf = 0; mf < 4; mf++)
        #pragma unroll
        for (int nf = 0; nf < 4; nf++) {
            int c = cbase + nf * 8;
            float b0 = bias[c], b1 = bias[c + 1];
            #pragma unroll
            for (int hh = 0; hh < 2; hh++) {
                int r = rbase + mf * 16 + hh * 8;
                float v0 = acc[mf][nf][2 * hh + 0] + b0;
                float v1 = acc[mf][nf][2 * hh + 1] + b1;
                if (mat == 2) {
                    g_V[head][r][c] = v0;
                    g_V[head][r][c + 1] = v1;
                } else {
                    __nv_bfloat16 h0, l0, h1, l1;
                    split1(v0, h0, l0); split1(v1, h1, l1);
                    *(__nv_bfloat162*)&outh[(size_t)r * HIDD + c] = __halves2bfloat162(h0, h1);
                    *(__nv_bfloat162*)&outl[(size_t)r * HIDD + c] = __halves2bfloat162(l0, l1);
                }
            }
        }
}

// ---------------------------------------------------------------------------
// tc scores: S = (Q @ K^T) * adj.  grid (32, 32, 2)
// ---------------------------------------------------------------------------
__global__ __launch_bounds__(256, 1) void tc_scores_kernel(const float* __restrict__ adj)
{
    extern __shared__ char smem[];
    const int head = blockIdx.z;
    const int m0 = blockIdx.y * 128;
    const int n0 = blockIdx.x * 128;

    float acc[4][4][4] = {};
    tc_mainloop(&g_Qh[head][0][0], &g_Ql[head][0][0], HIDD, m0,
                &g_Kh[head][0][0], &g_Kl[head][0][0], HIDD, n0,
                HIDD, smem, acc);

    const int lane = threadIdx.x & 31, wid = threadIdx.x >> 5;
    const int wm = wid >> 2, wn = wid & 3;
    const int rbase = m0 + wm * 64 + (lane >> 2);
    const int cbase = n0 + wn * 32 + (lane & 3) * 2;

    #pragma unroll
    for (int mf = 0; mf < 4; mf++)
        #pragma unroll
        for (int nf = 0; nf < 4; nf++) {
            int c = cbase + nf * 8;
            #pragma unroll
            for (int hh = 0; hh < 2; hh++) {
                int r = rbase + mf * 16 + hh * 8;
                float2 av = *(const float2*)&adj[((size_t)head * NN + r) * NN + c];
                float2 s;
                s.x = acc[mf][nf][2 * hh + 0] * av.x;
                s.y = acc[mf][nf][2 * hh + 1] * av.y;
                *(float2*)&g_S[head][r][c] = s;
            }
        }
}

// ---------------------------------------------------------------------------
// tc attnv: Xf = P @ V (via VT planes).  grid (2, 32, 2)
// ---------------------------------------------------------------------------
__global__ __launch_bounds__(256, 1) void tc_attnv_kernel()
{
    extern __shared__ char smem[];
    const int head = blockIdx.z;
    const int m0 = blockIdx.y * 128;
    const int n0 = blockIdx.x * 128;

    float acc[4][4][4] = {};
    tc_mainloop(&g_Ph[head][0][0], &g_Pl[head][0][0], NN, m0,
                &g_VTh[head][0][0], &g_VTl[head][0][0], NN, n0,
                NN, smem, acc);

    const int lane = threadIdx.x & 31, wid = threadIdx.x >> 5;
    const int wm = wid >> 2, wn = wid & 3;
    const int rbase = m0 + wm * 64 + (lane >> 2);
    const int cbase = head * HIDD + n0 + wn * 32 + (lane & 3) * 2;

    #pragma unroll
    for (int mf = 0; mf < 4; mf++)
        #pragma unroll
        for (int nf = 0; nf < 4; nf++) {
            int c = cbase + nf * 8;
            #pragma unroll
            for (int hh = 0; hh < 2; hh++) {
                int r = rbase + mf * 16 + hh * 8;
                float v0 = acc[mf][nf][2 * hh + 0];
                float v1 = acc[mf][nf][2 * hh + 1];
                __nv_bfloat16 h0, l0, h1, l1;
                split1(v0, h0, l0); split1(v1, h1, l1);
                *(__nv_bfloat162*)&g_Xfh[r][c] = __halves2bfloat162(h0, h1);
                *(__nv_bfloat162*)&g_Xfl[r][c] = __halves2bfloat162(l0, l1);
            }
        }
}

// ---------------------------------------------------------------------------
// tc z: z = Xf @ Wo + bo.  grid (4, 32, 1)
// ---------------------------------------------------------------------------
__global__ __launch_bounds__(256, 1) void tc_z_kernel(const float* __restrict__ bo)
{
    extern __shared__ char smem[];
    const int m0 = blockIdx.y * 128;
    const int n0 = blockIdx.x * 128;

    float acc[4][4][4] = {};
    tc_mainloop(&g_Xfh[0][0], &g_Xfl[0][0], IND, m0,
                &g_WoTh[0][0], &g_WoTl[0][0], 2 * HIDD, n0,
                2 * HIDD, smem, acc);

    const int lane = threadIdx.x & 31, wid = threadIdx.x >> 5;
    const int wm = wid >> 2, wn = wid & 3;
    const int rbase = m0 + wm * 64 + (lane >> 2);
    const int cbase = n0 + wn * 32 + (lane & 3) * 2;

    #pragma unroll
    for (int mf = 0; mf < 4; mf++)
        #pragma unroll
        for (int nf = 0; nf < 4; nf++) {
            int c = cbase + nf * 8;
            float b0 = bo[c], b1 = bo[c + 1];
            #pragma unroll
            for (int hh = 0; hh < 2; hh++) {
                int r = rbase + mf * 16 + hh * 8;
                g_z[r][c]     = acc[mf][nf][2 * hh + 0] + b0;
                g_z[r][c + 1] = acc[mf][nf][2 * hh + 1] + b1;
            }
        }
}

// ---------------------------------------------------------------------------
// Prep kernels
// ---------------------------------------------------------------------------
// h -> hi/lo planes
__global__ __launch_bounds__(256) void h_split_kernel(const float* __restrict__ h)
{
    int idx = blockIdx.x * 256 + threadIdx.x;       // float4 index
    float4 v = ((const float4*)h)[idx];
    uint2 hi, lo;
    cvt_hilo(v, hi, lo);
    ((uint2*)&g_hh[0][0])[idx] = hi;
    ((uint2*)&g_hl[0][0])[idx] = lo;
}

// Wq/Wk/Wv transpose+split: W[head][i][d] -> WT[mat*2+head][d][i]
__global__ __launch_bounds__(256) void wqkv_prep_kernel(
    const float* __restrict__ Wq, const float* __restrict__ Wk, const float* __restrict__ Wv)
{
    __shared__ float tile[32][33];
    const int zid = blockIdx.z;          // mat*2 + head
    const int mat = zid >> 1, head = zid & 1;
    const float* W = (mat == 0 ? Wq : (mat == 1 ? Wk : Wv)) + (size_t)head * IND * HIDD;
    const int i0 = blockIdx.x * 32, d0 = blockIdx.y * 32;
    const int tx = threadIdx.x, ty = threadIdx.y;
    #pragma unroll
    for (int k = 0; k < 32; k += 8)
        tile[ty + k][tx] = W[(size_t)(i0 + ty + k) * HIDD + d0 + tx];
    __syncthreads();
    #pragma unroll
    for (int k = 0; k < 32; k += 8) {
        float v = tile[tx][ty + k];
        __nv_bfloat16 h, l; split1(v, h, l);
        g_WTh[zid][d0 + ty + k][i0 + tx] = h;
        g_WTl[zid][d0 + ty + k][i0 + tx] = l;
    }
}

// Wo transpose+split: Wo[k][n] -> WoT[n][k]
__global__ __launch_bounds__(256) void wo_prep_kernel(const float* __restrict__ Wo)
{
    __shared__ float tile[32][33];
    const int k0 = blockIdx.x * 32, n0 = blockIdx.y * 32;
    const int tx = threadIdx.x, ty = threadIdx.y;
    #pragma unroll
    for (int k = 0; k < 32; k += 8)
        tile[ty + k][tx] = Wo[(size_t)(k0 + ty + k) * IND + n0 + tx];
    __syncthreads();
    #pragma unroll
    for (int k = 0; k < 32; k += 8) {
        float v = tile[tx][ty + k];
        __nv_bfloat16 h, l; split1(v, h, l);
        g_WoTh[n0 + ty + k][k0 + tx] = h;
        g_WoTl[n0 + ty + k][k0 + tx] = l;
    }
}

// V transpose+split: g_V[h][k][n] -> VT[h][n][k] hi/lo
__global__ __launch_bounds__(256) void vtrans_kernel()
{
    __shared__ float tile[32][33];
    const int h = blockIdx.z;
    const int k0 = blockIdx.x * 32, n0 = blockIdx.y * 32;
    const int tx = threadIdx.x, ty = threadIdx.y;
    #pragma unroll
    for (int i = 0; i < 32; i += 8)
        tile[ty + i][tx] = g_V[h][k0 + ty + i][n0 + tx];
    __syncthreads();
    #pragma unroll
    for (int i = 0; i < 32; i += 8) {
        float v = tile[tx][ty + i];
        __nv_bfloat16 hi, lo; split1(v, hi, lo);
        g_VTh[h][n0 + ty + i][k0 + tx] = hi;
        g_VTl[h][n0 + ty + i][k0 + tx] = lo;
    }
}

// ---------------------------------------------------------------------------
// Row softmax: g_S fp32 -> P hi/lo bf16 planes.  grid (4096, 2)
// ---------------------------------------------------------------------------
__global__ __launch_bounds__(256) void softmax_kernel()
{
    __shared__ float rowbuf[NN];
    __shared__ float red[256];

    const int head = blockIdx.y;
    const int row  = blockIdx.x;
    const float* S = &g_S[head][row][0];
    const int tid = threadIdx.x;

    float4* rb4 = (float4*)rowbuf;
    const float4* s4 = (const float4*)S;

    float lmax = -1e30f;
    for (int j = tid; j < NN / 4; j += 256) {
        float4 v = s4[j];
        rb4[j] = v;
        lmax = fmaxf(fmaxf(lmax, v.x), fmaxf(v.y, fmaxf(v.z, v.w)));
    }
    red[tid] = lmax;
    __syncthreads();
    for (int s = 128; s > 0; s >>= 1) {
        if (tid < s) red[tid] = fmaxf(red[tid], red[tid + s]);
        __syncthreads();
    }
    const float mx = red[0];
    __syncthreads();

    float lsum = 0.f;
    for (int j = tid; j < NN / 4; j += 256) {
        float4 v = rb4[j];
        v.x = __expf(v.x - mx); v.y = __expf(v.y - mx);
        v.z = __expf(v.z - mx); v.w = __expf(v.w - mx);
        rb4[j] = v;
        lsum += (v.x + v.y) + (v.z + v.w);
    }
    red[tid] = lsum;
    __syncthreads();
    for (int s = 128; s > 0; s >>= 1) {
        if (tid < s) red[tid] += red[tid + s];
        __syncthreads();
    }
    const float inv = 1.0f / red[0];

    uint2* ph = (uint2*)&g_Ph[head][row][0];
    uint2* pl = (uint2*)&g_Pl[head][row][0];
    for (int j = tid; j < NN / 4; j += 256) {
        float4 v = rb4[j];
        v.x *= inv; v.y *= inv; v.z *= inv; v.w *= inv;
        uint2 hi, lo;
        cvt_hilo(v, hi, lo);
        ph[j] = hi;
        pl[j] = lo;
    }
}

// ---------------------------------------------------------------------------
// Per-row LayerNorm -> M @ Wp + bp -> softmax(40). grid: 4096
// ---------------------------------------------------------------------------
__global__ __launch_bounds__(128) void lnproj_kernel(
    const float* __restrict__ gamma, const float* __restrict__ beta,
    const float* __restrict__ Wp, const float* __restrict__ bp,
    float* __restrict__ out)
{
    __shared__ float Ms[IND];
    __shared__ float red[128];
    __shared__ float lg[OUTD];

    const int row = blockIdx.x;
    const int tid = threadIdx.x;
    const float* z = &g_z[row][0];

    float s = 0.f, ss = 0.f;
    for (int j = tid; j < IND; j += 128) {
        float x = z[j];
        Ms[j] = x;
        s += x;
        ss += x * x;
    }
    red[tid] = s;
    __syncthreads();
    for (int k = 64; k > 0; k >>= 1) {
        if (tid < k) red[tid] += red[tid + k];
        __syncthreads();
    }
    const float mu = red[0] * (1.0f / IND);
    __syncthreads();
    red[tid] = ss;
    __syncthreads();
    for (int k = 64; k > 0; k >>= 1) {
        if (tid < k) red[tid] += red[tid + k];
        __syncthreads();
    }
    const float var  = red[0] * (1.0f / IND) - mu * mu;
    const float rstd = rsqrtf(var + LN_EPS);

    for (int j = tid; j < IND; j += 128)
        Ms[j] = (Ms[j] - mu) * rstd * gamma[j] + beta[j];
    __syncthreads();

    if (tid < OUTD) {
        float acc = bp[tid];
        #pragma unroll 8
        for (int j = 0; j < IND; j++)
            acc += Ms[j] * Wp[j * OUTD + tid];
        lg[tid] = acc;
    }
    __syncthreads();

    if (tid < OUTD) {
        float mx = -1e30f;
        #pragma unroll
        for (int o = 0; o < OUTD; o++) mx = fmaxf(mx, lg[o]);
        float sum = 0.f;
        #pragma unroll
        for (int o = 0; o < OUTD; o++) sum += __expf(lg[o] - mx);
        out[row * OUTD + tid] = __expf(lg[tid] - mx) / sum;
    }
}

// ---------------------------------------------------------------------------
extern "C" void kernel_launch(void* const* d_in, const int* in_sizes, int n_in,
                              void* d_out, int out_size)
{
    const float* adj   = (const float*)d_in[0];
    const float* h     = (const float*)d_in[1];
    const float* Wq    = (const float*)d_in[2];
    const float* bq    = (const float*)d_in[3];
    const float* Wk    = (const float*)d_in[4];
    const float* bk    = (const float*)d_in[5];
    const float* Wv    = (const float*)d_in[6];
    const float* bv    = (const float*)d_in[7];
    const float* Wo    = (const float*)d_in[8];
    const float* bo    = (const float*)d_in[9];
    const float* gamma = (const float*)d_in[10];
    const float* beta  = (const float*)d_in[11];
    const float* Wp    = (const float*)d_in[12];
    const float* bp    = (const float*)d_in[13];
    float* out = (float*)d_out;

    // host-side attribute set (idempotent, not an allocation, not a graph node)
    cudaFuncSetAttribute(tc_qkv_kernel,    cudaFuncAttributeMaxDynamicSharedMemorySize, TC_SMEM);
    cudaFuncSetAttribute(tc_scores_kernel, cudaFuncAttributeMaxDynamicSharedMemorySize, TC_SMEM);
    cudaFuncSetAttribute(tc_attnv_kernel,  cudaFuncAttributeMaxDynamicSharedMemorySize, TC_SMEM);
    cudaFuncSetAttribute(tc_z_kernel,      cudaFuncAttributeMaxDynamicSharedMemorySize, TC_SMEM);

    h_split_kernel<<<(NN * IND / 4) / 256, 256>>>(h);
    wqkv_prep_kernel<<<dim3(IND / 32, HIDD / 32, 6), dim3(32, 8)>>>(Wq, Wk, Wv);
    wo_prep_kernel<<<dim3(IND / 32, IND / 32), dim3(32, 8)>>>(Wo);

    tc_qkv_kernel<<<dim3(HIDD / 128, NN / 128, 6), 256, TC_SMEM>>>(bq, bk, bv);
    vtrans_kernel<<<dim3(NN / 32, HIDD / 32, NHEAD), dim3(32, 8)>>>();
    tc_scores_kernel<<<dim3(NN / 128, NN / 128, NHEAD), 256, TC_SMEM>>>(adj);
    softmax_kernel<<<dim3(NN, NHEAD), 256>>>();
    tc_attnv_kernel<<<dim3(HIDD / 128, NN / 128, NHEAD), 256, TC_SMEM>>>();
    tc_z_kernel<<<dim3(IND / 128, NN / 128), 256, TC_SMEM>>>(bo);
    lnproj_kernel<<<NN, 128>>>(gamma, beta, Wp, bp, out);
}

// round 7
// speedup vs baseline: 2.4725x; 1.1965x over previous
#include <cuda_runtime.h>
#include <cuda_bf16.h>
#include <cstdint>

#define NN     4096
#define IND    512
#define HIDD   256
#define NHEAD  2
#define OUTD   40
#define LN_EPS 1e-5f

// ---------------------------------------------------------------------------
// Static device scratch (no runtime allocation).
// ---------------------------------------------------------------------------
__device__ float          g_V [NHEAD][NN][HIDD];      // V fp32 (pre-transpose)
__device__ float          g_S [NHEAD][NN][NN];        // scores fp32
__device__ float          g_z [NN][IND];              // pre-LN activations
__device__ float          g_Xpart[2][NN][IND];        // attnv split-K partials
// bf16 hi/lo operand planes
__device__ __nv_bfloat16  g_hh[NN][IND],        g_hl[NN][IND];
__device__ __nv_bfloat16  g_Qh[NHEAD][NN][HIDD], g_Ql[NHEAD][NN][HIDD];
__device__ __nv_bfloat16  g_Kh[NHEAD][NN][HIDD], g_Kl[NHEAD][NN][HIDD];
__device__ __nv_bfloat16  g_VTh[NHEAD][HIDD][NN], g_VTl[NHEAD][HIDD][NN];
__device__ __nv_bfloat16  g_Ph[NHEAD][NN][NN],   g_Pl[NHEAD][NN][NN];
__device__ __nv_bfloat16  g_Xfh[NN][IND],        g_Xfl[NN][IND];
__device__ __nv_bfloat16  g_WTh[6][HIDD][IND],   g_WTl[6][HIDD][IND];   // qkv weights^T
__device__ __nv_bfloat16  g_WoTh[IND][2*HIDD],   g_WoTl[IND][2*HIDD];   // Wo^T

// ---------------------------------------------------------------------------
// Helpers
// ---------------------------------------------------------------------------
__device__ __forceinline__ uint32_t smem_to_u32(const void* p) {
    uint32_t a;
    asm("{ .reg .u64 t; cvta.to.shared.u64 t, %1; cvt.u32.u64 %0, t; }" : "=r"(a) : "l"(p));
    return a;
}
__device__ __forceinline__ void ldm4(uint32_t* r, uint32_t addr) {
    asm volatile("ldmatrix.sync.aligned.m8n8.x4.shared.b16 {%0,%1,%2,%3}, [%4];"
                 : "=r"(r[0]), "=r"(r[1]), "=r"(r[2]), "=r"(r[3]) : "r"(addr));
}
__device__ __forceinline__ void mma_bf16(float* d, const uint32_t* a, uint32_t b0, uint32_t b1) {
    asm volatile("mma.sync.aligned.m16n8k16.row.col.f32.bf16.bf16.f32 "
                 "{%0,%1,%2,%3}, {%4,%5,%6,%7}, {%8,%9}, {%0,%1,%2,%3};"
                 : "+f"(d[0]), "+f"(d[1]), "+f"(d[2]), "+f"(d[3])
                 : "r"(a[0]), "r"(a[1]), "r"(a[2]), "r"(a[3]), "r"(b0), "r"(b1));
}
__device__ __forceinline__ void cp_async16(uint32_t dst, const void* src) {
    asm volatile("cp.async.cg.shared.global [%0], [%1], 16;" :: "r"(dst), "l"(src));
}
#define CP_COMMIT() asm volatile("cp.async.commit_group;" ::: "memory")
#define CP_WAIT1()  asm volatile("cp.async.wait_group 1;" ::: "memory")

// fp32x4 -> packed bf16x2 hi + lo residual
__device__ __forceinline__ void cvt_hilo(float4 v, uint2& hi, uint2& lo) {
    uint32_t h01, h23;
    asm("cvt.rn.bf16x2.f32 %0, %1, %2;" : "=r"(h01) : "f"(v.y), "f"(v.x));
    asm("cvt.rn.bf16x2.f32 %0, %1, %2;" : "=r"(h23) : "f"(v.w), "f"(v.z));
    float hx = __uint_as_float(h01 << 16);
    float hy = __uint_as_float(h01 & 0xFFFF0000u);
    float hz = __uint_as_float(h23 << 16);
    float hw = __uint_as_float(h23 & 0xFFFF0000u);
    float lx = v.x - hx, ly = v.y - hy, lz = v.z - hz, lw = v.w - hw;
    uint32_t l01, l23;
    asm("cvt.rn.bf16x2.f32 %0, %1, %2;" : "=r"(l01) : "f"(ly), "f"(lx));
    asm("cvt.rn.bf16x2.f32 %0, %1, %2;" : "=r"(l23) : "f"(lw), "f"(lz));
    hi.x = h01; hi.y = h23;
    lo.x = l01; lo.y = l23;
}
__device__ __forceinline__ void split1(float v, __nv_bfloat16& h, __nv_bfloat16& l) {
    h = __float2bfloat16(v);
    l = __float2bfloat16(v - __bfloat162float(h));
}

// ---------------------------------------------------------------------------
// tc GEMM mainloop: acc[128x128] += A[128xK] * B[128xK]^T (hi/lo bf16 planes).
// Smem tile: 128 rows x 64B (32 k), XOR swizzle: 16B slot kg stored at
// kg ^ ((row>>1)&3). Conflict-free for cp.async stores and ldmatrix reads.
// 3-stage cp.async pipeline, 96KB smem total -> 2 CTAs/SM.
// 8 warps: wm = wid>>2, wn = wid&3; warp tile 64x32. 3-product bf16 split.
// ---------------------------------------------------------------------------
#define RS      64
#define TILE_B  (128 * RS)          // 8192 B per plane
#define STG_B   (4 * TILE_B)        // Ahi, Alo, Bhi, Blo = 32768 B
#define S_STG   3
#define TC_SMEM (S_STG * STG_B)     // 98304 B

__device__ __forceinline__ void tc_mainloop(
    const __nv_bfloat16* __restrict__ Ah, const __nv_bfloat16* __restrict__ Al,
    int lda, int m0,
    const __nv_bfloat16* __restrict__ Bh, const __nv_bfloat16* __restrict__ Bl,
    int ldb, int n0,
    int Kdim, char* smem, float acc[4][4][4])
{
    const int tid  = threadIdx.x;
    const int lane = tid & 31, wid = tid >> 5;
    const int wm = wid >> 2, wn = wid & 3;
    const uint32_t sb = smem_to_u32(smem);

    // one k-chunk (32 k = 64B/row): 4 planes x 128 rows x 4 16B-slots = 2048 cp
    #define TC_ISSUE(slot, kc)                                                   \
        { _Pragma("unroll")                                                      \
          for (int i = 0; i < 8; i++) {                                          \
              int lin = tid + i * 256;                                           \
              int plane = lin >> 9;                                              \
              int r = (lin >> 2) & 127;                                          \
              int kg = lin & 3;                                                  \
              const __nv_bfloat16* src;                                          \
              if (plane == 0)      src = &Ah[(size_t)(m0 + r) * lda + (kc) + kg * 8]; \
              else if (plane == 1) src = &Al[(size_t)(m0 + r) * lda + (kc) + kg * 8]; \
              else if (plane == 2) src = &Bh[(size_t)(n0 + r) * ldb + (kc) + kg * 8]; \
              else                 src = &Bl[(size_t)(n0 + r) * ldb + (kc) + kg * 8]; \
              uint32_t dst = sb + (uint32_t)(slot) * STG_B + plane * TILE_B      \
                             + r * RS + ((kg ^ ((r >> 1) & 3)) * 16);            \
              cp_async16(dst, src);                                              \
          }                                                                      \
          CP_COMMIT(); }

    const int T = Kdim / 32;
    TC_ISSUE(0, 0)
    TC_ISSUE(1, 32)

    for (int t = 0; t < T; t++) {
        CP_WAIT1();
        __syncthreads();
        if (t + 2 < T) {
            TC_ISSUE((t + 2) % S_STG, (t + 2) * 32)
        } else {
            CP_COMMIT();
        }

        const uint32_t stg = (uint32_t)(t % S_STG) * STG_B;
        #pragma unroll
        for (int ks = 0; ks < 2; ks++) {
            const int mat   = lane >> 3;
            const int chunk = ks * 2 + (mat >> 1);          // 16B slot index 0..3
            const int arow  = wm * 64 + ((mat & 1) << 3) + (lane & 7);
            const int brow  = wn * 32 + ((mat & 1) << 3) + (lane & 7);

            // pass 1: aH x bH
            uint32_t aH[4][4], bH[2][4];
            #pragma unroll
            for (int mf = 0; mf < 4; mf++) {
                int row = arow + mf * 16;
                ldm4(aH[mf], sb + stg + row * RS + ((chunk ^ ((row >> 1) & 3)) * 16));
            }
            #pragma unroll
            for (int p = 0; p < 2; p++) {
                int row = brow + p * 16;
                ldm4(bH[p], sb + stg + 2 * TILE_B + row * RS + ((chunk ^ ((row >> 1) & 3)) * 16));
            }
            #pragma unroll
            for (int mf = 0; mf < 4; mf++)
                #pragma unroll
                for (int nf = 0; nf < 4; nf++) {
                    int p = nf >> 1, q = nf & 1;
                    mma_bf16(acc[mf][nf], aH[mf], bH[p][q], bH[p][q + 2]);
                }

            // pass 2: aH x bL
            uint32_t bL[2][4];
            #pragma unroll
            for (int p = 0; p < 2; p++) {
                int row = brow + p * 16;
                ldm4(bL[p], sb + stg + 3 * TILE_B + row * RS + ((chunk ^ ((row >> 1) & 3)) * 16));
            }
            #pragma unroll
            for (int mf = 0; mf < 4; mf++)
                #pragma unroll
                for (int nf = 0; nf < 4; nf++) {
                    int p = nf >> 1, q = nf & 1;
                    mma_bf16(acc[mf][nf], aH[mf], bL[p][q], bL[p][q + 2]);
                }

            // pass 3: aL x bH
            uint32_t aL[4][4];
            #pragma unroll
            for (int mf = 0; mf < 4; mf++) {
                int row = arow + mf * 16;
                ldm4(aL[mf], sb + stg + TILE_B + row * RS + ((chunk ^ ((row >> 1) & 3)) * 16));
            }
            #pragma unroll
            for (int mf = 0; mf < 4; mf++)
                #pragma unroll
                for (int nf = 0; nf < 4; nf++) {
                    int p = nf >> 1, q = nf & 1;
                    mma_bf16(acc[mf][nf], aL[mf], bH[p][q], bH[p][q + 2]);
                }
        }
    }
    #undef TC_ISSUE
}

// ---------------------------------------------------------------------------
// tc qkv: {Q,K,V}[head] = h @ W + b.  grid (2, 32, 6)
// ---------------------------------------------------------------------------
__global__ __launch_bounds__(256, 2) void tc_qkv_kernel(
    const float* __restrict__ bq, const float* __restrict__ bk, const float* __restrict__ bv)
{
    extern __shared__ char smem[];
    const int mat  = blockIdx.z >> 1;
    const int head = blockIdx.z & 1;
    const int m0 = blockIdx.y * 128;
    const int n0 = blockIdx.x * 128;

    float acc[4][4][4] = {};
    tc_mainloop(&g_hh[0][0], &g_hl[0][0], IND, m0,
                &g_WTh[blockIdx.z][0][0], &g_WTl[blockIdx.z][0][0], IND, n0,
                IND, smem, acc);

    const float* bias = (mat == 0 ? bq : (mat == 1 ? bk : bv)) + head * HIDD;
    const int lane = threadIdx.x & 31, wid = threadIdx.x >> 5;
    const int wm = wid >> 2, wn = wid & 3;
    const int rbase = m0 + wm * 64 + (lane >> 2);
    const int cbase = n0 + wn * 32 + (lane & 3) * 2;

    __nv_bfloat16* outh = (mat == 0) ? &g_Qh[head][0][0] : &g_Kh[head][0][0];
    __nv_bfloat16* outl = (mat == 0) ? &g_Ql[head][0][0] : &g_Kl[head][0][0];

    #pragma unroll
    for (int mf = 0; mf < 4; mf++)
        #pragma unroll
        for (int nf = 0; nf < 4; nf++) {
            int c = cbase + nf * 8;
            float b0 = bias[c], b1 = bias[c + 1];
            #pragma unroll
            for (int hh = 0; hh < 2; hh++) {
                int r = rbase + mf * 16 + hh * 8;
                float v0 = acc[mf][nf][2 * hh + 0] + b0;
                float v1 = acc[mf][nf][2 * hh + 1] + b1;
                if (mat == 2) {
                    g_V[head][r][c] = v0;
                    g_V[head][r][c + 1] = v1;
                } else {
                    __nv_bfloat16 h0, l0, h1, l1;
                    split1(v0, h0, l0); split1(v1, h1, l1);
                    *(__nv_bfloat162*)&outh[(size_t)r * HIDD + c] = __halves2bfloat162(h0, h1);
                    *(__nv_bfloat162*)&outl[(size_t)r * HIDD + c] = __halves2bfloat162(l0, l1);
                }
            }
        }
}

// ---------------------------------------------------------------------------
// tc scores: S = (Q @ K^T) * adj.  grid (32, 32, 2)
// ---------------------------------------------------------------------------
__global__ __launch_bounds__(256, 2) void tc_scores_kernel(const float* __restrict__ adj)
{
    extern __shared__ char smem[];
    const int head = blockIdx.z;
    const int m0 = blockIdx.y * 128;
    const int n0 = blockIdx.x * 128;

    float acc[4][4][4] = {};
    tc_mainloop(&g_Qh[head][0][0], &g_Ql[head][0][0], HIDD, m0,
                &g_Kh[head][0][0], &g_Kl[head][0][0], HIDD, n0,
                HIDD, smem, acc);

    const int lane = threadIdx.x & 31, wid = threadIdx.x >> 5;
    const int wm = wid >> 2, wn = wid & 3;
    const int rbase = m0 + wm * 64 + (lane >> 2);
    const int cbase = n0 + wn * 32 + (lane & 3) * 2;

    #pragma unroll
    for (int mf = 0; mf < 4; mf++)
        #pragma unroll
        for (int nf = 0; nf < 4; nf++) {
            int c = cbase + nf * 8;
            #pragma unroll
            for (int hh = 0; hh < 2; hh++) {
                int r = rbase + mf * 16 + hh * 8;
                float2 av = *(const float2*)&adj[((size_t)head * NN + r) * NN + c];
                float2 s;
                s.x = acc[mf][nf][2 * hh + 0] * av.x;
                s.y = acc[mf][nf][2 * hh + 1] * av.y;
                *(float2*)&g_S[head][r][c] = s;
            }
        }
}

// ---------------------------------------------------------------------------
// tc attnv (split-K x2): Xpart[split] = P[:, ks] @ V[ks, :].  grid (2, 32, 4)
// blockIdx.z: head = z>>1, split = z&1
// ---------------------------------------------------------------------------
__global__ __launch_bounds__(256, 2) void tc_attnv_kernel()
{
    extern __shared__ char smem[];
    const int head  = blockIdx.z >> 1;
    const int split = blockIdx.z & 1;
    const int m0 = blockIdx.y * 128;
    const int n0 = blockIdx.x * 128;
    const int kbase = split * (NN / 2);

    float acc[4][4][4] = {};
    tc_mainloop(&g_Ph[head][0][kbase], &g_Pl[head][0][kbase], NN, m0,
                &g_VTh[head][0][kbase], &g_VTl[head][0][kbase], NN, n0,
                NN / 2, smem, acc);

    const int lane = threadIdx.x & 31, wid = threadIdx.x >> 5;
    const int wm = wid >> 2, wn = wid & 3;
    const int rbase = m0 + wm * 64 + (lane >> 2);
    const int cbase = head * HIDD + n0 + wn * 32 + (lane & 3) * 2;

    #pragma unroll
    for (int mf = 0; mf < 4; mf++)
        #pragma unroll
        for (int nf = 0; nf < 4; nf++) {
            int c = cbase + nf * 8;
            #pragma unroll
            for (int hh = 0; hh < 2; hh++) {
                int r = rbase + mf * 16 + hh * 8;
                g_Xpart[split][r][c]     = acc[mf][nf][2 * hh + 0];
                g_Xpart[split][r][c + 1] = acc[mf][nf][2 * hh + 1];
            }
        }
}

// reduce split-K partials -> Xf hi/lo planes.  grid 2048, 256 thr (float4)
__global__ __launch_bounds__(256) void xreduce_kernel()
{
    int idx = blockIdx.x * 256 + threadIdx.x;
    float4 a = ((const float4*)&g_Xpart[0][0][0])[idx];
    float4 b = ((const float4*)&g_Xpart[1][0][0])[idx];
    float4 v;
    v.x = a.x + b.x; v.y = a.y + b.y; v.z = a.z + b.z; v.w = a.w + b.w;
    uint2 hi, lo;
    cvt_hilo(v, hi, lo);
    ((uint2*)&g_Xfh[0][0])[idx] = hi;
    ((uint2*)&g_Xfl[0][0])[idx] = lo;
}

// ---------------------------------------------------------------------------
// tc z: z = Xf @ Wo + bo.  grid (4, 32)
// ---------------------------------------------------------------------------
__global__ __launch_bounds__(256, 2) void tc_z_kernel(const float* __restrict__ bo)
{
    extern __shared__ char smem[];
    const int m0 = blockIdx.y * 128;
    const int n0 = blockIdx.x * 128;

    float acc[4][4][4] = {};
    tc_mainloop(&g_Xfh[0][0], &g_Xfl[0][0], IND, m0,
                &g_WoTh[0][0], &g_WoTl[0][0], 2 * HIDD, n0,
                2 * HIDD, smem, acc);

    const int lane = threadIdx.x & 31, wid = threadIdx.x >> 5;
    const int wm = wid >> 2, wn = wid & 3;
    const int rbase = m0 + wm * 64 + (lane >> 2);
    const int cbase = n0 + wn * 32 + (lane & 3) * 2;

    #pragma unroll
    for (int mf = 0; mf < 4; mf++)
        #pragma unroll
        for (int nf = 0; nf < 4; nf++) {
            int c = cbase + nf * 8;
            float b0 = bo[c], b1 = bo[c + 1];
            #pragma unroll
            for (int hh = 0; hh < 2; hh++) {
                int r = rbase + mf * 16 + hh * 8;
                g_z[r][c]     = acc[mf][nf][2 * hh + 0] + b0;
                g_z[r][c + 1] = acc[mf][nf][2 * hh + 1] + b1;
            }
        }
}

// ---------------------------------------------------------------------------
// Prep kernels
// ---------------------------------------------------------------------------
__global__ __launch_bounds__(256) void h_split_kernel(const float* __restrict__ h)
{
    int idx = blockIdx.x * 256 + threadIdx.x;
    float4 v = ((const float4*)h)[idx];
    uint2 hi, lo;
    cvt_hilo(v, hi, lo);
    ((uint2*)&g_hh[0][0])[idx] = hi;
    ((uint2*)&g_hl[0][0])[idx] = lo;
}

__global__ __launch_bounds__(256) void wqkv_prep_kernel(
    const float* __restrict__ Wq, const float* __restrict__ Wk, const float* __restrict__ Wv)
{
    __shared__ float tile[32][33];
    const int zid = blockIdx.z;
    const int mat = zid >> 1, head = zid & 1;
    const float* W = (mat == 0 ? Wq : (mat == 1 ? Wk : Wv)) + (size_t)head * IND * HIDD;
    const int i0 = blockIdx.x * 32, d0 = blockIdx.y * 32;
    const int tx = threadIdx.x, ty = threadIdx.y;
    #pragma unroll
    for (int k = 0; k < 32; k += 8)
        tile[ty + k][tx] = W[(size_t)(i0 + ty + k) * HIDD + d0 + tx];
    __syncthreads();
    #pragma unroll
    for (int k = 0; k < 32; k += 8) {
        float v = tile[tx][ty + k];
        __nv_bfloat16 h, l; split1(v, h, l);
        g_WTh[zid][d0 + ty + k][i0 + tx] = h;
        g_WTl[zid][d0 + ty + k][i0 + tx] = l;
    }
}

__global__ __launch_bounds__(256) void wo_prep_kernel(const float* __restrict__ Wo)
{
    __shared__ float tile[32][33];
    const int k0 = blockIdx.x * 32, n0 = blockIdx.y * 32;
    const int tx = threadIdx.x, ty = threadIdx.y;
    #pragma unroll
    for (int k = 0; k < 32; k += 8)
        tile[ty + k][tx] = Wo[(size_t)(k0 + ty + k) * IND + n0 + tx];
    __syncthreads();
    #pragma unroll
    for (int k = 0; k < 32; k += 8) {
        float v = tile[tx][ty + k];
        __nv_bfloat16 h, l; split1(v, h, l);
        g_WoTh[n0 + ty + k][k0 + tx] = h;
        g_WoTl[n0 + ty + k][k0 + tx] = l;
    }
}

__global__ __launch_bounds__(256) void vtrans_kernel()
{
    __shared__ float tile[32][33];
    const int h = blockIdx.z;
    const int k0 = blockIdx.x * 32, n0 = blockIdx.y * 32;
    const int tx = threadIdx.x, ty = threadIdx.y;
    #pragma unroll
    for (int i = 0; i < 32; i += 8)
        tile[ty + i][tx] = g_V[h][k0 + ty + i][n0 + tx];
    __syncthreads();
    #pragma unroll
    for (int i = 0; i < 32; i += 8) {
        float v = tile[tx][ty + i];
        __nv_bfloat16 hi, lo; split1(v, hi, lo);
        g_VTh[h][n0 + ty + i][k0 + tx] = hi;
        g_VTl[h][n0 + ty + i][k0 + tx] = lo;
    }
}

// ---------------------------------------------------------------------------
// Row softmax: g_S fp32 -> P hi/lo bf16 planes.  grid (4096, 2)
// ---------------------------------------------------------------------------
__global__ __launch_bounds__(256) void softmax_kernel()
{
    __shared__ float rowbuf[NN];
    __shared__ float red[256];

    const int head = blockIdx.y;
    const int row  = blockIdx.x;
    const float* S = &g_S[head][row][0];
    const int tid = threadIdx.x;

    float4* rb4 = (float4*)rowbuf;
    const float4* s4 = (const float4*)S;

    float lmax = -1e30f;
    for (int j = tid; j < NN / 4; j += 256) {
        float4 v = s4[j];
        rb4[j] = v;
        lmax = fmaxf(fmaxf(lmax, v.x), fmaxf(v.y, fmaxf(v.z, v.w)));
    }
    red[tid] = lmax;
    __syncthreads();
    for (int s = 128; s > 0; s >>= 1) {
        if (tid < s) red[tid] = fmaxf(red[tid], red[tid + s]);
        __syncthreads();
    }
    const float mx = red[0];
    __syncthreads();

    float lsum = 0.f;
    for (int j = tid; j < NN / 4; j += 256) {
        float4 v = rb4[j];
        v.x = __expf(v.x - mx); v.y = __expf(v.y - mx);
        v.z = __expf(v.z - mx); v.w = __expf(v.w - mx);
        rb4[j] = v;
        lsum += (v.x + v.y) + (v.z + v.w);
    }
    red[tid] = lsum;
    __syncthreads();
    for (int s = 128; s > 0; s >>= 1) {
        if (tid < s) red[tid] += red[tid + s];
        __syncthreads();
    }
    const float inv = 1.0f / red[0];

    uint2* ph = (uint2*)&g_Ph[head][row][0];
    uint2* pl = (uint2*)&g_Pl[head][row][0];
    for (int j = tid; j < NN / 4; j += 256) {
        float4 v = rb4[j];
        v.x *= inv; v.y *= inv; v.z *= inv; v.w *= inv;
        uint2 hi, lo;
        cvt_hilo(v, hi, lo);
        ph[j] = hi;
        pl[j] = lo;
    }
}

// ---------------------------------------------------------------------------
// Per-row LayerNorm -> M @ Wp + bp -> softmax(40). grid: 4096
// ---------------------------------------------------------------------------
__global__ __launch_bounds__(128) void lnproj_kernel(
    const float* __restrict__ gamma, const float* __restrict__ beta,
    const float* __restrict__ Wp, const float* __restrict__ bp,
    float* __restrict__ out)
{
    __shared__ float Ms[IND];
    __shared__ float red[128];
    __shared__ float lg[OUTD];

    const int row = blockIdx.x;
    const int tid = threadIdx.x;
    const float* z = &g_z[row][0];

    float s = 0.f, ss = 0.f;
    for (int j = tid; j < IND; j += 128) {
        float x = z[j];
        Ms[j] = x;
        s += x;
        ss += x * x;
    }
    red[tid] = s;
    __syncthreads();
    for (int k = 64; k > 0; k >>= 1) {
        if (tid < k) red[tid] += red[tid + k];
        __syncthreads();
    }
    const float mu = red[0] * (1.0f / IND);
    __syncthreads();
    red[tid] = ss;
    __syncthreads();
    for (int k = 64; k > 0; k >>= 1) {
        if (tid < k) red[tid] += red[tid + k];
        __syncthreads();
    }
    const float var  = red[0] * (1.0f / IND) - mu * mu;
    const float rstd = rsqrtf(var + LN_EPS);

    for (int j = tid; j < IND; j += 128)
        Ms[j] = (Ms[j] - mu) * rstd * gamma[j] + beta[j];
    __syncthreads();

    if (tid < OUTD) {
        float acc = bp[tid];
        #pragma unroll 8
        for (int j = 0; j < IND; j++)
            acc += Ms[j] * Wp[j * OUTD + tid];
        lg[tid] = acc;
    }
    __syncthreads();

    if (tid < OUTD) {
        float mx = -1e30f;
        #pragma unroll
        for (int o = 0; o < OUTD; o++) mx = fmaxf(mx, lg[o]);
        float sum = 0.f;
        #pragma unroll
        for (int o = 0; o < OUTD; o++) sum += __expf(lg[o] - mx);
        out[row * OUTD + tid] = __expf(lg[tid] - mx) / sum;
    }
}

// ---------------------------------------------------------------------------
extern "C" void kernel_launch(void* const* d_in, const int* in_sizes, int n_in,
                              void* d_out, int out_size)
{
    const float* adj   = (const float*)d_in[0];
    const float* h     = (const float*)d_in[1];
    const float* Wq    = (const float*)d_in[2];
    const float* bq    = (const float*)d_in[3];
    const float* Wk    = (const float*)d_in[4];
    const float* bk    = (const float*)d_in[5];
    const float* Wv    = (const float*)d_in[6];
    const float* bv    = (const float*)d_in[7];
    const float* Wo    = (const float*)d_in[8];
    const float* bo    = (const float*)d_in[9];
    const float* gamma = (const float*)d_in[10];
    const float* beta  = (const float*)d_in[11];
    const float* Wp    = (const float*)d_in[12];
    const float* bp    = (const float*)d_in[13];
    float* out = (float*)d_out;

    cudaFuncSetAttribute(tc_qkv_kernel,    cudaFuncAttributeMaxDynamicSharedMemorySize, TC_SMEM);
    cudaFuncSetAttribute(tc_scores_kernel, cudaFuncAttributeMaxDynamicSharedMemorySize, TC_SMEM);
    cudaFuncSetAttribute(tc_attnv_kernel,  cudaFuncAttributeMaxDynamicSharedMemorySize, TC_SMEM);
    cudaFuncSetAttribute(tc_z_kernel,      cudaFuncAttributeMaxDynamicSharedMemorySize, TC_SMEM);

    h_split_kernel<<<(NN * IND / 4) / 256, 256>>>(h);
    wqkv_prep_kernel<<<dim3(IND / 32, HIDD / 32, 6), dim3(32, 8)>>>(Wq, Wk, Wv);
    wo_prep_kernel<<<dim3(IND / 32, IND / 32), dim3(32, 8)>>>(Wo);

    tc_qkv_kernel<<<dim3(HIDD / 128, NN / 128, 6), 256, TC_SMEM>>>(bq, bk, bv);
    vtrans_kernel<<<dim3(NN / 32, HIDD / 32, NHEAD), dim3(32, 8)>>>();
    tc_scores_kernel<<<dim3(NN / 128, NN / 128, NHEAD), 256, TC_SMEM>>>(adj);
    softmax_kernel<<<dim3(NN, NHEAD), 256>>>();
    tc_attnv_kernel<<<dim3(HIDD / 128, NN / 128, NHEAD * 2), 256, TC_SMEM>>>();
    xreduce_kernel<<<(NN * IND / 4) / 256, 256>>>();
    tc_z_kernel<<<dim3(IND / 128, NN / 128), 256, TC_SMEM>>>(bo);
    lnproj_kernel<<<NN, 128>>>(gamma, beta, Wp, bp, out);
}

// round 8
// speedup vs baseline: 2.4875x; 1.0060x over previous
#include <cuda_runtime.h>
#include <cuda_bf16.h>
#include <cstdint>

#define NN     4096
#define IND    512
#define HIDD   256
#define NHEAD  2
#define OUTD   40
#define LN_EPS 1e-5f

// ---------------------------------------------------------------------------
// Static device scratch (no runtime allocation).
// ---------------------------------------------------------------------------
__device__ float          g_V [NHEAD][NN][HIDD];      // V fp32 (pre-transpose)
__device__ float          g_S [NHEAD][NN][NN];        // scores fp32
__device__ float          g_z [NN][IND];              // pre-LN activations
__device__ float          g_Xpart[2][NN][IND];        // attnv split-K partials
// bf16 hi/lo operand planes
__device__ __nv_bfloat16  g_hh[NN][IND],        g_hl[NN][IND];
__device__ __nv_bfloat16  g_Qh[NHEAD][NN][HIDD], g_Ql[NHEAD][NN][HIDD];
__device__ __nv_bfloat16  g_Kh[NHEAD][NN][HIDD], g_Kl[NHEAD][NN][HIDD];
__device__ __nv_bfloat16  g_VTh[NHEAD][HIDD][NN], g_VTl[NHEAD][HIDD][NN];
__device__ __nv_bfloat16  g_Ph[NHEAD][NN][NN],   g_Pl[NHEAD][NN][NN];
__device__ __nv_bfloat16  g_Xfh[NN][IND],        g_Xfl[NN][IND];
__device__ __nv_bfloat16  g_WTh[6][HIDD][IND],   g_WTl[6][HIDD][IND];   // qkv weights^T
__device__ __nv_bfloat16  g_WoTh[IND][2*HIDD],   g_WoTl[IND][2*HIDD];   // Wo^T

// ---------------------------------------------------------------------------
// Helpers
// ---------------------------------------------------------------------------
__device__ __forceinline__ uint32_t smem_to_u32(const void* p) {
    uint32_t a;
    asm("{ .reg .u64 t; cvta.to.shared.u64 t, %1; cvt.u32.u64 %0, t; }" : "=r"(a) : "l"(p));
    return a;
}
__device__ __forceinline__ void ldm4(uint32_t* r, uint32_t addr) {
    asm volatile("ldmatrix.sync.aligned.m8n8.x4.shared.b16 {%0,%1,%2,%3}, [%4];"
                 : "=r"(r[0]), "=r"(r[1]), "=r"(r[2]), "=r"(r[3]) : "r"(addr));
}
__device__ __forceinline__ void mma_bf16(float* d, const uint32_t* a, uint32_t b0, uint32_t b1) {
    asm volatile("mma.sync.aligned.m16n8k16.row.col.f32.bf16.bf16.f32 "
                 "{%0,%1,%2,%3}, {%4,%5,%6,%7}, {%8,%9}, {%0,%1,%2,%3};"
                 : "+f"(d[0]), "+f"(d[1]), "+f"(d[2]), "+f"(d[3])
                 : "r"(a[0]), "r"(a[1]), "r"(a[2]), "r"(a[3]), "r"(b0), "r"(b1));
}
__device__ __forceinline__ void cp_async16(uint32_t dst, const void* src) {
    asm volatile("cp.async.cg.shared.global [%0], [%1], 16;" :: "r"(dst), "l"(src));
}
#define CP_COMMIT() asm volatile("cp.async.commit_group;" ::: "memory")
#define CP_WAIT1()  asm volatile("cp.async.wait_group 1;" ::: "memory")

// fp32x4 -> packed bf16x2 hi + lo residual
__device__ __forceinline__ void cvt_hilo(float4 v, uint2& hi, uint2& lo) {
    uint32_t h01, h23;
    asm("cvt.rn.bf16x2.f32 %0, %1, %2;" : "=r"(h01) : "f"(v.y), "f"(v.x));
    asm("cvt.rn.bf16x2.f32 %0, %1, %2;" : "=r"(h23) : "f"(v.w), "f"(v.z));
    float hx = __uint_as_float(h01 << 16);
    float hy = __uint_as_float(h01 & 0xFFFF0000u);
    float hz = __uint_as_float(h23 << 16);
    float hw = __uint_as_float(h23 & 0xFFFF0000u);
    float lx = v.x - hx, ly = v.y - hy, lz = v.z - hz, lw = v.w - hw;
    uint32_t l01, l23;
    asm("cvt.rn.bf16x2.f32 %0, %1, %2;" : "=r"(l01) : "f"(ly), "f"(lx));
    asm("cvt.rn.bf16x2.f32 %0, %1, %2;" : "=r"(l23) : "f"(lw), "f"(lz));
    hi.x = h01; hi.y = h23;
    lo.x = l01; lo.y = l23;
}
__device__ __forceinline__ void split1(float v, __nv_bfloat16& h, __nv_bfloat16& l) {
    h = __float2bfloat16(v);
    l = __float2bfloat16(v - __bfloat162float(h));
}

// ---------------------------------------------------------------------------
// tc GEMM mainloop: acc[128x128] += A[128xK] * B[128xK]^T (hi/lo bf16 planes).
// Smem tile: 128 rows x 64B (32 k), XOR swizzle (kg ^ ((row>>1)&3)).
// 3-stage cp.async pipeline, 96KB smem -> 2 CTAs/SM.
// 8 warps: warp tile 64x32; 3-product bf16 split with software-pipelined
// fragment loads (bL issued under aH*bH MMAs, aL under aH*bL MMAs).
// ---------------------------------------------------------------------------
#define RS      64
#define TILE_B  (128 * RS)          // 8192 B per plane
#define STG_B   (4 * TILE_B)        // Ahi, Alo, Bhi, Blo = 32768 B
#define S_STG   3
#define TC_SMEM (S_STG * STG_B)     // 98304 B

__device__ __forceinline__ void tc_mainloop(
    const __nv_bfloat16* __restrict__ Ah, const __nv_bfloat16* __restrict__ Al,
    int lda, int m0,
    const __nv_bfloat16* __restrict__ Bh, const __nv_bfloat16* __restrict__ Bl,
    int ldb, int n0,
    int Kdim, char* smem, float acc[4][4][4])
{
    const int tid  = threadIdx.x;
    const int lane = tid & 31, wid = tid >> 5;
    const int wm = wid >> 2, wn = wid & 3;
    const uint32_t sb = smem_to_u32(smem);

    // precomputed ldmatrix row addressing (stage- and chunk-independent parts)
    const int mat  = lane >> 3;                 // 0..3
    const int cadd = mat >> 1;                  // chunk sub-index from lane
    uint32_t a_base[4], b_base[2];
    int a_sw[4], b_sw[2];
    #pragma unroll
    for (int mf = 0; mf < 4; mf++) {
        int row = wm * 64 + mf * 16 + ((mat & 1) << 3) + (lane & 7);
        a_base[mf] = row * RS;
        a_sw[mf]   = (row >> 1) & 3;
    }
    #pragma unroll
    for (int p = 0; p < 2; p++) {
        int row = wn * 32 + p * 16 + ((mat & 1) << 3) + (lane & 7);
        b_base[p] = row * RS;
        b_sw[p]   = (row >> 1) & 3;
    }

    #define TC_ISSUE(slot, kc)                                                   \
        { _Pragma("unroll")                                                      \
          for (int i = 0; i < 8; i++) {                                          \
              int lin = tid + i * 256;                                           \
              int plane = lin >> 9;                                              \
              int r = (lin >> 2) & 127;                                          \
              int kg = lin & 3;                                                  \
              const __nv_bfloat16* src;                                          \
              if (plane == 0)      src = &Ah[(size_t)(m0 + r) * lda + (kc) + kg * 8]; \
              else if (plane == 1) src = &Al[(size_t)(m0 + r) * lda + (kc) + kg * 8]; \
              else if (plane == 2) src = &Bh[(size_t)(n0 + r) * ldb + (kc) + kg * 8]; \
              else                 src = &Bl[(size_t)(n0 + r) * ldb + (kc) + kg * 8]; \
              uint32_t dst = sb + (uint32_t)(slot) * STG_B + plane * TILE_B      \
                             + r * RS + ((kg ^ ((r >> 1) & 3)) * 16);            \
              cp_async16(dst, src);                                              \
          }                                                                      \
          CP_COMMIT(); }

    const int T = Kdim / 32;
    TC_ISSUE(0, 0)
    TC_ISSUE(1, 32)

    for (int t = 0; t < T; t++) {
        CP_WAIT1();
        __syncthreads();
        if (t + 2 < T) {
            TC_ISSUE((t + 2) % S_STG, (t + 2) * 32)
        } else {
            CP_COMMIT();
        }

        const uint32_t stg = (uint32_t)(t % S_STG) * STG_B;
        #pragma unroll
        for (int ks = 0; ks < 2; ks++) {
            const int chunk = ks * 2 + cadd;     // 16B slot 0..3

            uint32_t aH[4][4], aL[4][4], bH[2][4], bL[2][4];
            // fragment loads for product 1
            #pragma unroll
            for (int mf = 0; mf < 4; mf++)
                ldm4(aH[mf], sb + stg + a_base[mf] + (((chunk ^ a_sw[mf]) & 3) * 16));
            #pragma unroll
            for (int p = 0; p < 2; p++)
                ldm4(bH[p], sb + stg + 2 * TILE_B + b_base[p] + (((chunk ^ b_sw[p]) & 3) * 16));
            // prefetch bL under product-1 MMAs
            #pragma unroll
            for (int p = 0; p < 2; p++)
                ldm4(bL[p], sb + stg + 3 * TILE_B + b_base[p] + (((chunk ^ b_sw[p]) & 3) * 16));

            #pragma unroll
            for (int mf = 0; mf < 4; mf++)
                #pragma unroll
                for (int nf = 0; nf < 4; nf++) {
                    int p = nf >> 1, q = nf & 1;
                    mma_bf16(acc[mf][nf], aH[mf], bH[p][q], bH[p][q + 2]);
                }

            // prefetch aL under product-2 MMAs
            #pragma unroll
            for (int mf = 0; mf < 4; mf++)
                ldm4(aL[mf], sb + stg + TILE_B + a_base[mf] + (((chunk ^ a_sw[mf]) & 3) * 16));

            #pragma unroll
            for (int mf = 0; mf < 4; mf++)
                #pragma unroll
                for (int nf = 0; nf < 4; nf++) {
                    int p = nf >> 1, q = nf & 1;
                    mma_bf16(acc[mf][nf], aH[mf], bL[p][q], bL[p][q + 2]);
                }

            #pragma unroll
            for (int mf = 0; mf < 4; mf++)
                #pragma unroll
                for (int nf = 0; nf < 4; nf++) {
                    int p = nf >> 1, q = nf & 1;
                    mma_bf16(acc[mf][nf], aL[mf], bH[p][q], bH[p][q + 2]);
                }
        }
    }
    #undef TC_ISSUE
}

// ---------------------------------------------------------------------------
// tc qkv: {Q,K,V}[head] = h @ W + b.  grid (2, 32, 6)
// ---------------------------------------------------------------------------
__global__ __launch_bounds__(256, 2) void tc_qkv_kernel(
    const float* __restrict__ bq, const float* __restrict__ bk, const float* __restrict__ bv)
{
    extern __shared__ char smem[];
    const int mat  = blockIdx.z >> 1;
    const int head = blockIdx.z & 1;
    const int m0 = blockIdx.y * 128;
    const int n0 = blockIdx.x * 128;

    float acc[4][4][4] = {};
    tc_mainloop(&g_hh[0][0], &g_hl[0][0], IND, m0,
                &g_WTh[blockIdx.z][0][0], &g_WTl[blockIdx.z][0][0], IND, n0,
                IND, smem, acc);

    const float* bias = (mat == 0 ? bq : (mat == 1 ? bk : bv)) + head * HIDD;
    const int lane = threadIdx.x & 31, wid = threadIdx.x >> 5;
    const int wm = wid >> 2, wn = wid & 3;
    const int rbase = m0 + wm * 64 + (lane >> 2);
    const int cbase = n0 + wn * 32 + (lane & 3) * 2;

    __nv_bfloat16* outh = (mat == 0) ? &g_Qh[head][0][0] : &g_Kh[head][0][0];
    __nv_bfloat16* outl = (mat == 0) ? &g_Ql[head][0][0] : &g_Kl[head][0][0];

    #pragma unroll
    for (int mf = 0; mf < 4; mf++)
        #pragma unroll
        for (int nf = 0; nf < 4; nf++) {
            int c = cbase + nf * 8;
            float b0 = bias[c], b1 = bias[c + 1];
            #pragma unroll
            for (int hh = 0; hh < 2; hh++) {
                int r = rbase + mf * 16 + hh * 8;
                float v0 = acc[mf][nf][2 * hh + 0] + b0;
                float v1 = acc[mf][nf][2 * hh + 1] + b1;
                if (mat == 2) {
                    g_V[head][r][c] = v0;
                    g_V[head][r][c + 1] = v1;
                } else {
                    __nv_bfloat16 h0, l0, h1, l1;
                    split1(v0, h0, l0); split1(v1, h1, l1);
                    *(__nv_bfloat162*)&outh[(size_t)r * HIDD + c] = __halves2bfloat162(h0, h1);
                    *(__nv_bfloat162*)&outl[(size_t)r * HIDD + c] = __halves2bfloat162(l0, l1);
                }
            }
        }
}

// ---------------------------------------------------------------------------
// tc scores: S = (Q @ K^T) * adj.  grid (32, 32, 2)
// ---------------------------------------------------------------------------
__global__ __launch_bounds__(256, 2) void tc_scores_kernel(const float* __restrict__ adj)
{
    extern __shared__ char smem[];
    const int head = blockIdx.z;
    const int m0 = blockIdx.y * 128;
    const int n0 = blockIdx.x * 128;

    float acc[4][4][4] = {};
    tc_mainloop(&g_Qh[head][0][0], &g_Ql[head][0][0], HIDD, m0,
                &g_Kh[head][0][0], &g_Kl[head][0][0], HIDD, n0,
                HIDD, smem, acc);

    const int lane = threadIdx.x & 31, wid = threadIdx.x >> 5;
    const int wm = wid >> 2, wn = wid & 3;
    const int rbase = m0 + wm * 64 + (lane >> 2);
    const int cbase = n0 + wn * 32 + (lane & 3) * 2;

    #pragma unroll
    for (int mf = 0; mf < 4; mf++)
        #pragma unroll
        for (int nf = 0; nf < 4; nf++) {
            int c = cbase + nf * 8;
            #pragma unroll
            for (int hh = 0; hh < 2; hh++) {
                int r = rbase + mf * 16 + hh * 8;
                float2 av = *(const float2*)&adj[((size_t)head * NN + r) * NN + c];
                float2 s;
                s.x = acc[mf][nf][2 * hh + 0] * av.x;
                s.y = acc[mf][nf][2 * hh + 1] * av.y;
                *(float2*)&g_S[head][r][c] = s;
            }
        }
}

// ---------------------------------------------------------------------------
// tc attnv (split-K x2): grid (2, 32, 4); head = z>>1, split = z&1
// ---------------------------------------------------------------------------
__global__ __launch_bounds__(256, 2) void tc_attnv_kernel()
{
    extern __shared__ char smem[];
    const int head  = blockIdx.z >> 1;
    const int split = blockIdx.z & 1;
    const int m0 = blockIdx.y * 128;
    const int n0 = blockIdx.x * 128;
    const int kbase = split * (NN / 2);

    float acc[4][4][4] = {};
    tc_mainloop(&g_Ph[head][0][kbase], &g_Pl[head][0][kbase], NN, m0,
                &g_VTh[head][0][kbase], &g_VTl[head][0][kbase], NN, n0,
                NN / 2, smem, acc);

    const int lane = threadIdx.x & 31, wid = threadIdx.x >> 5;
    const int wm = wid >> 2, wn = wid & 3;
    const int rbase = m0 + wm * 64 + (lane >> 2);
    const int cbase = head * HIDD + n0 + wn * 32 + (lane & 3) * 2;

    #pragma unroll
    for (int mf = 0; mf < 4; mf++)
        #pragma unroll
        for (int nf = 0; nf < 4; nf++) {
            int c = cbase + nf * 8;
            #pragma unroll
            for (int hh = 0; hh < 2; hh++) {
                int r = rbase + mf * 16 + hh * 8;
                g_Xpart[split][r][c]     = acc[mf][nf][2 * hh + 0];
                g_Xpart[split][r][c + 1] = acc[mf][nf][2 * hh + 1];
            }
        }
}

// reduce split-K partials -> Xf hi/lo planes.  grid 2048, 256 thr (float4)
__global__ __launch_bounds__(256) void xreduce_kernel()
{
    int idx = blockIdx.x * 256 + threadIdx.x;
    float4 a = ((const float4*)&g_Xpart[0][0][0])[idx];
    float4 b = ((const float4*)&g_Xpart[1][0][0])[idx];
    float4 v;
    v.x = a.x + b.x; v.y = a.y + b.y; v.z = a.z + b.z; v.w = a.w + b.w;
    uint2 hi, lo;
    cvt_hilo(v, hi, lo);
    ((uint2*)&g_Xfh[0][0])[idx] = hi;
    ((uint2*)&g_Xfl[0][0])[idx] = lo;
}

// ---------------------------------------------------------------------------
// tc z: z = Xf @ Wo + bo.  grid (4, 32)
// ---------------------------------------------------------------------------
__global__ __launch_bounds__(256, 2) void tc_z_kernel(const float* __restrict__ bo)
{
    extern __shared__ char smem[];
    const int m0 = blockIdx.y * 128;
    const int n0 = blockIdx.x * 128;

    float acc[4][4][4] = {};
    tc_mainloop(&g_Xfh[0][0], &g_Xfl[0][0], IND, m0,
                &g_WoTh[0][0], &g_WoTl[0][0], 2 * HIDD, n0,
                2 * HIDD, smem, acc);

    const int lane = threadIdx.x & 31, wid = threadIdx.x >> 5;
    const int wm = wid >> 2, wn = wid & 3;
    const int rbase = m0 + wm * 64 + (lane >> 2);
    const int cbase = n0 + wn * 32 + (lane & 3) * 2;

    #pragma unroll
    for (int mf = 0; mf < 4; mf++)
        #pragma unroll
        for (int nf = 0; nf < 4; nf++) {
            int c = cbase + nf * 8;
            float b0 = bo[c], b1 = bo[c + 1];
            #pragma unroll
            for (int hh = 0; hh < 2; hh++) {
                int r = rbase + mf * 16 + hh * 8;
                g_z[r][c]     = acc[mf][nf][2 * hh + 0] + b0;
                g_z[r][c + 1] = acc[mf][nf][2 * hh + 1] + b1;
            }
        }
}

// ---------------------------------------------------------------------------
// Prep kernels
// ---------------------------------------------------------------------------
__global__ __launch_bounds__(256) void h_split_kernel(const float* __restrict__ h)
{
    int idx = blockIdx.x * 256 + threadIdx.x;
    float4 v = ((const float4*)h)[idx];
    uint2 hi, lo;
    cvt_hilo(v, hi, lo);
    ((uint2*)&g_hh[0][0])[idx] = hi;
    ((uint2*)&g_hl[0][0])[idx] = lo;
}

__global__ __launch_bounds__(256) void wqkv_prep_kernel(
    const float* __restrict__ Wq, const float* __restrict__ Wk, const float* __restrict__ Wv)
{
    __shared__ float tile[32][33];
    const int zid = blockIdx.z;
    const int mat = zid >> 1, head = zid & 1;
    const float* W = (mat == 0 ? Wq : (mat == 1 ? Wk : Wv)) + (size_t)head * IND * HIDD;
    const int i0 = blockIdx.x * 32, d0 = blockIdx.y * 32;
    const int tx = threadIdx.x, ty = threadIdx.y;
    #pragma unroll
    for (int k = 0; k < 32; k += 8)
        tile[ty + k][tx] = W[(size_t)(i0 + ty + k) * HIDD + d0 + tx];
    __syncthreads();
    #pragma unroll
    for (int k = 0; k < 32; k += 8) {
        float v = tile[tx][ty + k];
        __nv_bfloat16 h, l; split1(v, h, l);
        g_WTh[zid][d0 + ty + k][i0 + tx] = h;
        g_WTl[zid][d0 + ty + k][i0 + tx] = l;
    }
}

__global__ __launch_bounds__(256) void wo_prep_kernel(const float* __restrict__ Wo)
{
    __shared__ float tile[32][33];
    const int k0 = blockIdx.x * 32, n0 = blockIdx.y * 32;
    const int tx = threadIdx.x, ty = threadIdx.y;
    #pragma unroll
    for (int k = 0; k < 32; k += 8)
        tile[ty + k][tx] = Wo[(size_t)(k0 + ty + k) * IND + n0 + tx];
    __syncthreads();
    #pragma unroll
    for (int k = 0; k < 32; k += 8) {
        float v = tile[tx][ty + k];
        __nv_bfloat16 h, l; split1(v, h, l);
        g_WoTh[n0 + ty + k][k0 + tx] = h;
        g_WoTl[n0 + ty + k][k0 + tx] = l;
    }
}

__global__ __launch_bounds__(256) void vtrans_kernel()
{
    __shared__ float tile[32][33];
    const int h = blockIdx.z;
    const int k0 = blockIdx.x * 32, n0 = blockIdx.y * 32;
    const int tx = threadIdx.x, ty = threadIdx.y;
    #pragma unroll
    for (int i = 0; i < 32; i += 8)
        tile[ty + i][tx] = g_V[h][k0 + ty + i][n0 + tx];
    __syncthreads();
    #pragma unroll
    for (int i = 0; i < 32; i += 8) {
        float v = tile[tx][ty + i];
        __nv_bfloat16 hi, lo; split1(v, hi, lo);
        g_VTh[h][n0 + ty + i][k0 + tx] = hi;
        g_VTl[h][n0 + ty + i][k0 + tx] = lo;
    }
}

// ---------------------------------------------------------------------------
// Row softmax: g_S fp32 -> P hi/lo bf16 planes.  grid (4096, 2)
// ---------------------------------------------------------------------------
__global__ __launch_bounds__(256) void softmax_kernel()
{
    __shared__ float rowbuf[NN];
    __shared__ float red[256];

    const int head = blockIdx.y;
    const int row  = blockIdx.x;
    const float* S = &g_S[head][row][0];
    const int tid = threadIdx.x;

    float4* rb4 = (float4*)rowbuf;
    const float4* s4 = (const float4*)S;

    float lmax = -1e30f;
    for (int j = tid; j < NN / 4; j += 256) {
        float4 v = s4[j];
        rb4[j] = v;
        lmax = fmaxf(fmaxf(lmax, v.x), fmaxf(v.y, fmaxf(v.z, v.w)));
    }
    red[tid] = lmax;
    __syncthreads();
    for (int s = 128; s > 0; s >>= 1) {
        if (tid < s) red[tid] = fmaxf(red[tid], red[tid + s]);
        __syncthreads();
    }
    const float mx = red[0];
    __syncthreads();

    float lsum = 0.f;
    for (int j = tid; j < NN / 4; j += 256) {
        float4 v = rb4[j];
        v.x = __expf(v.x - mx); v.y = __expf(v.y - mx);
        v.z = __expf(v.z - mx); v.w = __expf(v.w - mx);
        rb4[j] = v;
        lsum += (v.x + v.y) + (v.z + v.w);
    }
    red[tid] = lsum;
    __syncthreads();
    for (int s = 128; s > 0; s >>= 1) {
        if (tid < s) red[tid] += red[tid + s];
        __syncthreads();
    }
    const float inv = 1.0f / red[0];

    uint2* ph = (uint2*)&g_Ph[head][row][0];
    uint2* pl = (uint2*)&g_Pl[head][row][0];
    for (int j = tid; j < NN / 4; j += 256) {
        float4 v = rb4[j];
        v.x *= inv; v.y *= inv; v.z *= inv; v.w *= inv;
        uint2 hi, lo;
        cvt_hilo(v, hi, lo);
        ph[j] = hi;
        pl[j] = lo;
    }
}

// ---------------------------------------------------------------------------
// Per-row LayerNorm -> M @ Wp + bp -> softmax(40). grid: 4096
// ---------------------------------------------------------------------------
__global__ __launch_bounds__(128) void lnproj_kernel(
    const float* __restrict__ gamma, const float* __restrict__ beta,
    const float* __restrict__ Wp, const float* __restrict__ bp,
    float* __restrict__ out)
{
    __shared__ float Ms[IND];
    __shared__ float red[128];
    __shared__ float lg[OUTD];

    const int row = blockIdx.x;
    const int tid = threadIdx.x;
    const float* z = &g_z[row][0];

    float s = 0.f, ss = 0.f;
    for (int j = tid; j < IND; j += 128) {
        float x = z[j];
        Ms[j] = x;
        s += x;
        ss += x * x;
    }
    red[tid] = s;
    __syncthreads();
    for (int k = 64; k > 0; k >>= 1) {
        if (tid < k) red[tid] += red[tid + k];
        __syncthreads();
    }
    const float mu = red[0] * (1.0f / IND);
    __syncthreads();
    red[tid] = ss;
    __syncthreads();
    for (int k = 64; k > 0; k >>= 1) {
        if (tid < k) red[tid] += red[tid + k];
        __syncthreads();
    }
    const float var  = red[0] * (1.0f / IND) - mu * mu;
    const float rstd = rsqrtf(var + LN_EPS);

    for (int j = tid; j < IND; j += 128)
        Ms[j] = (Ms[j] - mu) * rstd * gamma[j] + beta[j];
    __syncthreads();

    if (tid < OUTD) {
        float acc = bp[tid];
        #pragma unroll 8
        for (int j = 0; j < IND; j++)
            acc += Ms[j] * Wp[j * OUTD + tid];
        lg[tid] = acc;
    }
    __syncthreads();

    if (tid < OUTD) {
        float mx = -1e30f;
        #pragma unroll
        for (int o = 0; o < OUTD; o++) mx = fmaxf(mx, lg[o]);
        float sum = 0.f;
        #pragma unroll
        for (int o = 0; o < OUTD; o++) sum += __expf(lg[o] - mx);
        out[row * OUTD + tid] = __expf(lg[tid] - mx) / sum;
    }
}

// ---------------------------------------------------------------------------
extern "C" void kernel_launch(void* const* d_in, const int* in_sizes, int n_in,
                              void* d_out, int out_size)
{
    const float* adj   = (const float*)d_in[0];
    const float* h     = (const float*)d_in[1];
    const float* Wq    = (const float*)d_in[2];
    const float* bq    = (const float*)d_in[3];
    const float* Wk    = (const float*)d_in[4];
    const float* bk    = (const float*)d_in[5];
    const float* Wv    = (const float*)d_in[6];
    const float* bv    = (const float*)d_in[7];
    const float* Wo    = (const float*)d_in[8];
    const float* bo    = (const float*)d_in[9];
    const float* gamma = (const float*)d_in[10];
    const float* beta  = (const float*)d_in[11];
    const float* Wp    = (const float*)d_in[12];
    const float* bp    = (const float*)d_in[13];
    float* out = (float*)d_out;

    cudaFuncSetAttribute(tc_qkv_kernel,    cudaFuncAttributeMaxDynamicSharedMemorySize, TC_SMEM);
    cudaFuncSetAttribute(tc_scores_kernel, cudaFuncAttributeMaxDynamicSharedMemorySize, TC_SMEM);
    cudaFuncSetAttribute(tc_attnv_kernel,  cudaFuncAttributeMaxDynamicSharedMemorySize, TC_SMEM);
    cudaFuncSetAttribute(tc_z_kernel,      cudaFuncAttributeMaxDynamicSharedMemorySize, TC_SMEM);

    h_split_kernel<<<(NN * IND / 4) / 256, 256>>>(h);
    wqkv_prep_kernel<<<dim3(IND / 32, HIDD / 32, 6), dim3(32, 8)>>>(Wq, Wk, Wv);
    wo_prep_kernel<<<dim3(IND / 32, IND / 32), dim3(32, 8)>>>(Wo);

    tc_qkv_kernel<<<dim3(HIDD / 128, NN / 128, 6), 256, TC_SMEM>>>(bq, bk, bv);
    vtrans_kernel<<<dim3(NN / 32, HIDD / 32, NHEAD), dim3(32, 8)>>>();
    tc_scores_kernel<<<dim3(NN / 128, NN / 128, NHEAD), 256, TC_SMEM>>>(adj);
    softmax_kernel<<<dim3(NN, NHEAD), 256>>>();
    tc_attnv_kernel<<<dim3(HIDD / 128, NN / 128, NHEAD * 2), 256, TC_SMEM>>>();
    xreduce_kernel<<<(NN * IND / 4) / 256, 256>>>();
    tc_z_kernel<<<dim3(IND / 128, NN / 128), 256, TC_SMEM>>>(bo);
    lnproj_kernel<<<NN, 128>>>(gamma, beta, Wp, bp, out);
}

// round 9
// speedup vs baseline: 2.5064x; 1.0076x over previous
#include <cuda_runtime.h>
#include <cuda_bf16.h>
#include <cstdint>

#define NN     4096
#define IND    512
#define HIDD   256
#define NHEAD  2
#define OUTD   40
#define LN_EPS 1e-5f

// ---------------------------------------------------------------------------
// Static device scratch (no runtime allocation).
// ---------------------------------------------------------------------------
__device__ float          g_V [NHEAD][NN][HIDD];      // V fp32 (pre-transpose)
__device__ float          g_S [NHEAD][NN][NN];        // scores fp32
__device__ float          g_z [NN][IND];              // pre-LN activations
__device__ float          g_Xpart[2][NN][IND];        // attnv split-K partials
// bf16 hi/lo operand planes
__device__ __nv_bfloat16  g_hh[NN][IND],        g_hl[NN][IND];
__device__ __nv_bfloat16  g_Qh[NHEAD][NN][HIDD], g_Ql[NHEAD][NN][HIDD];
__device__ __nv_bfloat16  g_Kh[NHEAD][NN][HIDD], g_Kl[NHEAD][NN][HIDD];
__device__ __nv_bfloat16  g_VTh[NHEAD][HIDD][NN], g_VTl[NHEAD][HIDD][NN];
__device__ __nv_bfloat16  g_Ph[NHEAD][NN][NN],   g_Pl[NHEAD][NN][NN];
__device__ __nv_bfloat16  g_Xfh[NN][IND],        g_Xfl[NN][IND];
__device__ __nv_bfloat16  g_WTh[6][HIDD][IND],   g_WTl[6][HIDD][IND];   // qkv weights^T
__device__ __nv_bfloat16  g_WoTh[IND][2*HIDD],   g_WoTl[IND][2*HIDD];   // Wo^T

// ---------------------------------------------------------------------------
// Helpers
// ---------------------------------------------------------------------------
__device__ __forceinline__ uint32_t smem_to_u32(const void* p) {
    uint32_t a;
    asm("{ .reg .u64 t; cvta.to.shared.u64 t, %1; cvt.u32.u64 %0, t; }" : "=r"(a) : "l"(p));
    return a;
}
__device__ __forceinline__ void ldm4(uint32_t* r, uint32_t addr) {
    asm volatile("ldmatrix.sync.aligned.m8n8.x4.shared.b16 {%0,%1,%2,%3}, [%4];"
                 : "=r"(r[0]), "=r"(r[1]), "=r"(r[2]), "=r"(r[3]) : "r"(addr));
}
__device__ __forceinline__ void mma_bf16(float* d, const uint32_t* a, uint32_t b0, uint32_t b1) {
    asm volatile("mma.sync.aligned.m16n8k16.row.col.f32.bf16.bf16.f32 "
                 "{%0,%1,%2,%3}, {%4,%5,%6,%7}, {%8,%9}, {%0,%1,%2,%3};"
                 : "+f"(d[0]), "+f"(d[1]), "+f"(d[2]), "+f"(d[3])
                 : "r"(a[0]), "r"(a[1]), "r"(a[2]), "r"(a[3]), "r"(b0), "r"(b1));
}
__device__ __forceinline__ void cp_async16(uint32_t dst, const void* src) {
    asm volatile("cp.async.cg.shared.global [%0], [%1], 16;" :: "r"(dst), "l"(src));
}
#define CP_COMMIT() asm volatile("cp.async.commit_group;" ::: "memory")
#define CP_WAIT1()  asm volatile("cp.async.wait_group 1;" ::: "memory")

// fp32x4 -> packed bf16x2 hi + lo residual
__device__ __forceinline__ void cvt_hilo(float4 v, uint2& hi, uint2& lo) {
    uint32_t h01, h23;
    asm("cvt.rn.bf16x2.f32 %0, %1, %2;" : "=r"(h01) : "f"(v.y), "f"(v.x));
    asm("cvt.rn.bf16x2.f32 %0, %1, %2;" : "=r"(h23) : "f"(v.w), "f"(v.z));
    float hx = __uint_as_float(h01 << 16);
    float hy = __uint_as_float(h01 & 0xFFFF0000u);
    float hz = __uint_as_float(h23 << 16);
    float hw = __uint_as_float(h23 & 0xFFFF0000u);
    float lx = v.x - hx, ly = v.y - hy, lz = v.z - hz, lw = v.w - hw;
    uint32_t l01, l23;
    asm("cvt.rn.bf16x2.f32 %0, %1, %2;" : "=r"(l01) : "f"(ly), "f"(lx));
    asm("cvt.rn.bf16x2.f32 %0, %1, %2;" : "=r"(l23) : "f"(lw), "f"(lz));
    hi.x = h01; hi.y = h23;
    lo.x = l01; lo.y = l23;
}
__device__ __forceinline__ void split1(float v, __nv_bfloat16& h, __nv_bfloat16& l) {
    h = __float2bfloat16(v);
    l = __float2bfloat16(v - __bfloat162float(h));
}

// ---------------------------------------------------------------------------
// tc GEMM mainloop: acc[128x128] += A[128xK] * B[128xK]^T (hi/lo bf16 planes).
// Smem tile: 128 rows x 64B (32 k), XOR swizzle (kg ^ ((row>>1)&3)).
// 3-stage cp.async pipeline, 96KB smem -> 2 CTAs/SM.
// All hot-loop addressing strength-reduced: each thread owns one fixed cp.async
// plane with a single advancing pointer; ldmatrix uses 4 precomputed bases
// (A/B x ks-parity) since the swizzle slot is invariant across mf/p.
// ---------------------------------------------------------------------------
#define RS      64
#define TILE_B  (128 * RS)          // 8192 B per plane
#define STG_B   (4 * TILE_B)        // Ahi, Alo, Bhi, Blo = 32768 B
#define S_STG   3
#define TC_SMEM (S_STG * STG_B)     // 98304 B

__device__ __forceinline__ void tc_mainloop(
    const __nv_bfloat16* __restrict__ Ah, const __nv_bfloat16* __restrict__ Al,
    int lda, int m0,
    const __nv_bfloat16* __restrict__ Bh, const __nv_bfloat16* __restrict__ Bl,
    int ldb, int n0,
    int Kdim, char* smem, float acc[4][4][4])
{
    const int tid  = threadIdx.x;
    const int lane = tid & 31, wid = tid >> 5;
    const int wm = wid >> 2, wn = wid & 3;
    const uint32_t sb = smem_to_u32(smem);

    // ---- cp.async: fixed plane per thread ----
    const int plane = tid >> 6;          // 0:Ah 1:Al 2:Bh 3:Bl
    const int tl    = tid & 63;
    const int r0    = tl >> 2;           // row 0..15 (steps of 16 via i)
    const int kg    = tl & 3;            // 16B slot in row
    const __nv_bfloat16* gsrc;
    int ldX;
    if (plane == 0)      { gsrc = Ah + (size_t)(m0 + r0) * lda + kg * 8; ldX = lda; }
    else if (plane == 1) { gsrc = Al + (size_t)(m0 + r0) * lda + kg * 8; ldX = lda; }
    else if (plane == 2) { gsrc = Bh + (size_t)(n0 + r0) * ldb + kg * 8; ldX = ldb; }
    else                 { gsrc = Bl + (size_t)(n0 + r0) * ldb + kg * 8; ldX = ldb; }
    const uint32_t dst0 = sb + plane * TILE_B + r0 * RS + ((kg ^ ((r0 >> 1) & 3)) * 16);

    // ---- ldmatrix: precomputed bases (slot swizzle invariant across mf/p) ----
    const int mat  = lane >> 3;
    const int cadd = mat >> 1;
    const int a_row0 = wm * 64 + ((mat & 1) << 3) + (lane & 7);
    const int b_row0 = wn * 32 + ((mat & 1) << 3) + (lane & 7);
    const int a_sw = (a_row0 >> 1) & 3, b_sw = (b_row0 >> 1) & 3;
    uint32_t aBase[2], bBase[2];
    aBase[0] = sb + a_row0 * RS + ((cadd ^ a_sw) & 3) * 16;
    aBase[1] = sb + a_row0 * RS + ((cadd ^ 2 ^ a_sw) & 3) * 16;
    bBase[0] = sb + 2 * TILE_B + b_row0 * RS + ((cadd ^ b_sw) & 3) * 16;
    bBase[1] = sb + 2 * TILE_B + b_row0 * RS + ((cadd ^ 2 ^ b_sw) & 3) * 16;

    #define TC_ISSUE(slotbytes)                                                  \
        { const uint32_t _d = dst0 + (slotbytes);                                \
          _Pragma("unroll")                                                      \
          for (int i = 0; i < 8; i++)                                            \
              cp_async16(_d + i * 1024, gsrc + (size_t)i * 16 * ldX);            \
          CP_COMMIT();                                                           \
          gsrc += 32; }

    const int T = Kdim / 32;
    TC_ISSUE(0)
    TC_ISSUE(STG_B)

    uint32_t stg = 0;                      // consume slot bytes
    uint32_t isl = 2 * STG_B;              // issue slot bytes (t+2)
    for (int t = 0; t < T; t++) {
        CP_WAIT1();
        __syncthreads();
        if (t + 2 < T) {
            TC_ISSUE(isl)
            isl += STG_B; if (isl == S_STG * STG_B) isl = 0;
        } else {
            CP_COMMIT();
        }

        #pragma unroll
        for (int ks = 0; ks < 2; ks++) {
            const uint32_t aA = aBase[ks] + stg;
            const uint32_t bA = bBase[ks] + stg;

            uint32_t aH[4][4], aL[4][4], bH[2][4], bL[2][4];
            #pragma unroll
            for (int mf = 0; mf < 4; mf++) ldm4(aH[mf], aA + mf * 1024);
            #pragma unroll
            for (int p = 0; p < 2; p++)    ldm4(bH[p], bA + p * 1024);
            #pragma unroll
            for (int p = 0; p < 2; p++)    ldm4(bL[p], bA + TILE_B + p * 1024);

            #pragma unroll
            for (int mf = 0; mf < 4; mf++)
                #pragma unroll
                for (int nf = 0; nf < 4; nf++) {
                    int p = nf >> 1, q = nf & 1;
                    mma_bf16(acc[mf][nf], aH[mf], bH[p][q], bH[p][q + 2]);
                }

            #pragma unroll
            for (int mf = 0; mf < 4; mf++) ldm4(aL[mf], aA + TILE_B + mf * 1024);

            #pragma unroll
            for (int mf = 0; mf < 4; mf++)
                #pragma unroll
                for (int nf = 0; nf < 4; nf++) {
                    int p = nf >> 1, q = nf & 1;
                    mma_bf16(acc[mf][nf], aH[mf], bL[p][q], bL[p][q + 2]);
                }

            #pragma unroll
            for (int mf = 0; mf < 4; mf++)
                #pragma unroll
                for (int nf = 0; nf < 4; nf++) {
                    int p = nf >> 1, q = nf & 1;
                    mma_bf16(acc[mf][nf], aL[mf], bH[p][q], bH[p][q + 2]);
                }
        }
        stg += STG_B; if (stg == S_STG * STG_B) stg = 0;
    }
    #undef TC_ISSUE
}

// ---------------------------------------------------------------------------
// tc qkv: {Q,K,V}[head] = h @ W + b.  grid (2, 32, 6)
// ---------------------------------------------------------------------------
__global__ __launch_bounds__(256, 2) void tc_qkv_kernel(
    const float* __restrict__ bq, const float* __restrict__ bk, const float* __restrict__ bv)
{
    extern __shared__ char smem[];
    const int mat  = blockIdx.z >> 1;
    const int head = blockIdx.z & 1;
    const int m0 = blockIdx.y * 128;
    const int n0 = blockIdx.x * 128;

    float acc[4][4][4] = {};
    tc_mainloop(&g_hh[0][0], &g_hl[0][0], IND, m0,
                &g_WTh[blockIdx.z][0][0], &g_WTl[blockIdx.z][0][0], IND, n0,
                IND, smem, acc);

    const float* bias = (mat == 0 ? bq : (mat == 1 ? bk : bv)) + head * HIDD;
    const int lane = threadIdx.x & 31, wid = threadIdx.x >> 5;
    const int wm = wid >> 2, wn = wid & 3;
    const int rbase = m0 + wm * 64 + (lane >> 2);
    const int cbase = n0 + wn * 32 + (lane & 3) * 2;

    __nv_bfloat16* outh = (mat == 0) ? &g_Qh[head][0][0] : &g_Kh[head][0][0];
    __nv_bfloat16* outl = (mat == 0) ? &g_Ql[head][0][0] : &g_Kl[head][0][0];

    #pragma unroll
    for (int mf = 0; mf < 4; mf++)
        #pragma unroll
        for (int nf = 0; nf < 4; nf++) {
            int c = cbase + nf * 8;
            float b0 = bias[c], b1 = bias[c + 1];
            #pragma unroll
            for (int hh = 0; hh < 2; hh++) {
                int r = rbase + mf * 16 + hh * 8;
                float v0 = acc[mf][nf][2 * hh + 0] + b0;
                float v1 = acc[mf][nf][2 * hh + 1] + b1;
                if (mat == 2) {
                    g_V[head][r][c] = v0;
                    g_V[head][r][c + 1] = v1;
                } else {
                    __nv_bfloat16 h0, l0, h1, l1;
                    split1(v0, h0, l0); split1(v1, h1, l1);
                    *(__nv_bfloat162*)&outh[(size_t)r * HIDD + c] = __halves2bfloat162(h0, h1);
                    *(__nv_bfloat162*)&outl[(size_t)r * HIDD + c] = __halves2bfloat162(l0, l1);
                }
            }
        }
}

// ---------------------------------------------------------------------------
// tc scores: S = (Q @ K^T) * adj.  grid (32, 32, 2)
// ---------------------------------------------------------------------------
__global__ __launch_bounds__(256, 2) void tc_scores_kernel(const float* __restrict__ adj)
{
    extern __shared__ char smem[];
    const int head = blockIdx.z;
    const int m0 = blockIdx.y * 128;
    const int n0 = blockIdx.x * 128;

    float acc[4][4][4] = {};
    tc_mainloop(&g_Qh[head][0][0], &g_Ql[head][0][0], HIDD, m0,
                &g_Kh[head][0][0], &g_Kl[head][0][0], HIDD, n0,
                HIDD, smem, acc);

    const int lane = threadIdx.x & 31, wid = threadIdx.x >> 5;
    const int wm = wid >> 2, wn = wid & 3;
    const int rbase = m0 + wm * 64 + (lane >> 2);
    const int cbase = n0 + wn * 32 + (lane & 3) * 2;

    #pragma unroll
    for (int mf = 0; mf < 4; mf++)
        #pragma unroll
        for (int nf = 0; nf < 4; nf++) {
            int c = cbase + nf * 8;
            #pragma unroll
            for (int hh = 0; hh < 2; hh++) {
                int r = rbase + mf * 16 + hh * 8;
                float2 av = *(const float2*)&adj[((size_t)head * NN + r) * NN + c];
                float2 s;
                s.x = acc[mf][nf][2 * hh + 0] * av.x;
                s.y = acc[mf][nf][2 * hh + 1] * av.y;
                *(float2*)&g_S[head][r][c] = s;
            }
        }
}

// ---------------------------------------------------------------------------
// tc attnv (split-K x2): grid (2, 32, 4); head = z>>1, split = z&1
// ---------------------------------------------------------------------------
__global__ __launch_bounds__(256, 2) void tc_attnv_kernel()
{
    extern __shared__ char smem[];
    const int head  = blockIdx.z >> 1;
    const int split = blockIdx.z & 1;
    const int m0 = blockIdx.y * 128;
    const int n0 = blockIdx.x * 128;
    const int kbase = split * (NN / 2);

    float acc[4][4][4] = {};
    tc_mainloop(&g_Ph[head][0][kbase], &g_Pl[head][0][kbase], NN, m0,
                &g_VTh[head][0][kbase], &g_VTl[head][0][kbase], NN, n0,
                NN / 2, smem, acc);

    const int lane = threadIdx.x & 31, wid = threadIdx.x >> 5;
    const int wm = wid >> 2, wn = wid & 3;
    const int rbase = m0 + wm * 64 + (lane >> 2);
    const int cbase = head * HIDD + n0 + wn * 32 + (lane & 3) * 2;

    #pragma unroll
    for (int mf = 0; mf < 4; mf++)
        #pragma unroll
        for (int nf = 0; nf < 4; nf++) {
            int c = cbase + nf * 8;
            #pragma unroll
            for (int hh = 0; hh < 2; hh++) {
                int r = rbase + mf * 16 + hh * 8;
                g_Xpart[split][r][c]     = acc[mf][nf][2 * hh + 0];
                g_Xpart[split][r][c + 1] = acc[mf][nf][2 * hh + 1];
            }
        }
}

// reduce split-K partials -> Xf hi/lo planes.  grid 2048, 256 thr (float4)
__global__ __launch_bounds__(256) void xreduce_kernel()
{
    int idx = blockIdx.x * 256 + threadIdx.x;
    float4 a = ((const float4*)&g_Xpart[0][0][0])[idx];
    float4 b = ((const float4*)&g_Xpart[1][0][0])[idx];
    float4 v;
    v.x = a.x + b.x; v.y = a.y + b.y; v.z = a.z + b.z; v.w = a.w + b.w;
    uint2 hi, lo;
    cvt_hilo(v, hi, lo);
    ((uint2*)&g_Xfh[0][0])[idx] = hi;
    ((uint2*)&g_Xfl[0][0])[idx] = lo;
}

// ---------------------------------------------------------------------------
// tc z: z = Xf @ Wo + bo.  grid (4, 32)
// ---------------------------------------------------------------------------
__global__ __launch_bounds__(256, 2) void tc_z_kernel(const float* __restrict__ bo)
{
    extern __shared__ char smem[];
    const int m0 = blockIdx.y * 128;
    const int n0 = blockIdx.x * 128;

    float acc[4][4][4] = {};
    tc_mainloop(&g_Xfh[0][0], &g_Xfl[0][0], IND, m0,
                &g_WoTh[0][0], &g_WoTl[0][0], 2 * HIDD, n0,
                2 * HIDD, smem, acc);

    const int lane = threadIdx.x & 31, wid = threadIdx.x >> 5;
    const int wm = wid >> 2, wn = wid & 3;
    const int rbase = m0 + wm * 64 + (lane >> 2);
    const int cbase = n0 + wn * 32 + (lane & 3) * 2;

    #pragma unroll
    for (int mf = 0; mf < 4; mf++)
        #pragma unroll
        for (int nf = 0; nf < 4; nf++) {
            int c = cbase + nf * 8;
            float b0 = bo[c], b1 = bo[c + 1];
            #pragma unroll
            for (int hh = 0; hh < 2; hh++) {
                int r = rbase + mf * 16 + hh * 8;
                g_z[r][c]     = acc[mf][nf][2 * hh + 0] + b0;
                g_z[r][c + 1] = acc[mf][nf][2 * hh + 1] + b1;
            }
        }
}

// ---------------------------------------------------------------------------
// Prep kernels
// ---------------------------------------------------------------------------
__global__ __launch_bounds__(256) void h_split_kernel(const float* __restrict__ h)
{
    int idx = blockIdx.x * 256 + threadIdx.x;
    float4 v = ((const float4*)h)[idx];
    uint2 hi, lo;
    cvt_hilo(v, hi, lo);
    ((uint2*)&g_hh[0][0])[idx] = hi;
    ((uint2*)&g_hl[0][0])[idx] = lo;
}

__global__ __launch_bounds__(256) void wqkv_prep_kernel(
    const float* __restrict__ Wq, const float* __restrict__ Wk, const float* __restrict__ Wv)
{
    __shared__ float tile[32][33];
    const int zid = blockIdx.z;
    const int mat = zid >> 1, head = zid & 1;
    const float* W = (mat == 0 ? Wq : (mat == 1 ? Wk : Wv)) + (size_t)head * IND * HIDD;
    const int i0 = blockIdx.x * 32, d0 = blockIdx.y * 32;
    const int tx = threadIdx.x, ty = threadIdx.y;
    #pragma unroll
    for (int k = 0; k < 32; k += 8)
        tile[ty + k][tx] = W[(size_t)(i0 + ty + k) * HIDD + d0 + tx];
    __syncthreads();
    #pragma unroll
    for (int k = 0; k < 32; k += 8) {
        float v = tile[tx][ty + k];
        __nv_bfloat16 h, l; split1(v, h, l);
        g_WTh[zid][d0 + ty + k][i0 + tx] = h;
        g_WTl[zid][d0 + ty + k][i0 + tx] = l;
    }
}

__global__ __launch_bounds__(256) void wo_prep_kernel(const float* __restrict__ Wo)
{
    __shared__ float tile[32][33];
    const int k0 = blockIdx.x * 32, n0 = blockIdx.y * 32;
    const int tx = threadIdx.x, ty = threadIdx.y;
    #pragma unroll
    for (int k = 0; k < 32; k += 8)
        tile[ty + k][tx] = Wo[(size_t)(k0 + ty + k) * IND + n0 + tx];
    __syncthreads();
    #pragma unroll
    for (int k = 0; k < 32; k += 8) {
        float v = tile[tx][ty + k];
        __nv_bfloat16 h, l; split1(v, h, l);
        g_WoTh[n0 + ty + k][k0 + tx] = h;
        g_WoTl[n0 + ty + k][k0 + tx] = l;
    }
}

__global__ __launch_bounds__(256) void vtrans_kernel()
{
    __shared__ float tile[32][33];
    const int h = blockIdx.z;
    const int k0 = blockIdx.x * 32, n0 = blockIdx.y * 32;
    const int tx = threadIdx.x, ty = threadIdx.y;
    #pragma unroll
    for (int i = 0; i < 32; i += 8)
        tile[ty + i][tx] = g_V[h][k0 + ty + i][n0 + tx];
    __syncthreads();
    #pragma unroll
    for (int i = 0; i < 32; i += 8) {
        float v = tile[tx][ty + i];
        __nv_bfloat16 hi, lo; split1(v, hi, lo);
        g_VTh[h][n0 + ty + i][k0 + tx] = hi;
        g_VTl[h][n0 + ty + i][k0 + tx] = lo;
    }
}

// ---------------------------------------------------------------------------
// Row softmax: g_S fp32 -> P hi/lo bf16 planes.  grid (4096, 2)
// ---------------------------------------------------------------------------
__global__ __launch_bounds__(256) void softmax_kernel()
{
    __shared__ float rowbuf[NN];
    __shared__ float red[256];

    const int head = blockIdx.y;
    const int row  = blockIdx.x;
    const float* S = &g_S[head][row][0];
    const int tid = threadIdx.x;

    float4* rb4 = (float4*)rowbuf;
    const float4* s4 = (const float4*)S;

    float lmax = -1e30f;
    for (int j = tid; j < NN / 4; j += 256) {
        float4 v = s4[j];
        rb4[j] = v;
        lmax = fmaxf(fmaxf(lmax, v.x), fmaxf(v.y, fmaxf(v.z, v.w)));
    }
    red[tid] = lmax;
    __syncthreads();
    for (int s = 128; s > 0; s >>= 1) {
        if (tid < s) red[tid] = fmaxf(red[tid], red[tid + s]);
        __syncthreads();
    }
    const float mx = red[0];
    __syncthreads();

    float lsum = 0.f;
    for (int j = tid; j < NN / 4; j += 256) {
        float4 v = rb4[j];
        v.x = __expf(v.x - mx); v.y = __expf(v.y - mx);
        v.z = __expf(v.z - mx); v.w = __expf(v.w - mx);
        rb4[j] = v;
        lsum += (v.x + v.y) + (v.z + v.w);
    }
    red[tid] = lsum;
    __syncthreads();
    for (int s = 128; s > 0; s >>= 1) {
        if (tid < s) red[tid] += red[tid + s];
        __syncthreads();
    }
    const float inv = 1.0f / red[0];

    uint2* ph = (uint2*)&g_Ph[head][row][0];
    uint2* pl = (uint2*)&g_Pl[head][row][0];
    for (int j = tid; j < NN / 4; j += 256) {
        float4 v = rb4[j];
        v.x *= inv; v.y *= inv; v.z *= inv; v.w *= inv;
        uint2 hi, lo;
        cvt_hilo(v, hi, lo);
        ph[j] = hi;
        pl[j] = lo;
    }
}

// ---------------------------------------------------------------------------
// Per-row LayerNorm -> M @ Wp + bp -> softmax(40). grid: 4096
// ---------------------------------------------------------------------------
__global__ __launch_bounds__(128) void lnproj_kernel(
    const float* __restrict__ gamma, const float* __restrict__ beta,
    const float* __restrict__ Wp, const float* __restrict__ bp,
    float* __restrict__ out)
{
    __shared__ float Ms[IND];
    __shared__ float red[128];
    __shared__ float lg[OUTD];

    const int row = blockIdx.x;
    const int tid = threadIdx.x;
    const float* z = &g_z[row][0];

    float s = 0.f, ss = 0.f;
    for (int j = tid; j < IND; j += 128) {
        float x = z[j];
        Ms[j] = x;
        s += x;
        ss += x * x;
    }
    red[tid] = s;
    __syncthreads();
    for (int k = 64; k > 0; k >>= 1) {
        if (tid < k) red[tid] += red[tid + k];
        __syncthreads();
    }
    const float mu = red[0] * (1.0f / IND);
    __syncthreads();
    red[tid] = ss;
    __syncthreads();
    for (int k = 64; k > 0; k >>= 1) {
        if (tid < k) red[tid] += red[tid + k];
        __syncthreads();
    }
    const float var  = red[0] * (1.0f / IND) - mu * mu;
    const float rstd = rsqrtf(var + LN_EPS);

    for (int j = tid; j < IND; j += 128)
        Ms[j] = (Ms[j] - mu) * rstd * gamma[j] + beta[j];
    __syncthreads();

    if (tid < OUTD) {
        float acc = bp[tid];
        #pragma unroll 8
        for (int j = 0; j < IND; j++)
            acc += Ms[j] * Wp[j * OUTD + tid];
        lg[tid] = acc;
    }
    __syncthreads();

    if (tid < OUTD) {
        float mx = -1e30f;
        #pragma unroll
        for (int o = 0; o < OUTD; o++) mx = fmaxf(mx, lg[o]);
        float sum = 0.f;
        #pragma unroll
        for (int o = 0; o < OUTD; o++) sum += __expf(lg[o] - mx);
        out[row * OUTD + tid] = __expf(lg[tid] - mx) / sum;
    }
}

// ---------------------------------------------------------------------------
extern "C" void kernel_launch(void* const* d_in, const int* in_sizes, int n_in,
                              void* d_out, int out_size)
{
    const float* adj   = (const float*)d_in[0];
    const float* h     = (const float*)d_in[1];
    const float* Wq    = (const float*)d_in[2];
    const float* bq    = (const float*)d_in[3];
    const float* Wk    = (const float*)d_in[4];
    const float* bk    = (const float*)d_in[5];
    const float* Wv    = (const float*)d_in[6];
    const float* bv    = (const float*)d_in[7];
    const float* Wo    = (const float*)d_in[8];
    const float* bo    = (const float*)d_in[9];
    const float* gamma = (const float*)d_in[10];
    const float* beta  = (const float*)d_in[11];
    const float* Wp    = (const float*)d_in[12];
    const float* bp    = (const float*)d_in[13];
    float* out = (float*)d_out;

    cudaFuncSetAttribute(tc_qkv_kernel,    cudaFuncAttributeMaxDynamicSharedMemorySize, TC_SMEM);
    cudaFuncSetAttribute(tc_scores_kernel, cudaFuncAttributeMaxDynamicSharedMemorySize, TC_SMEM);
    cudaFuncSetAttribute(tc_attnv_kernel,  cudaFuncAttributeMaxDynamicSharedMemorySize, TC_SMEM);
    cudaFuncSetAttribute(tc_z_kernel,      cudaFuncAttributeMaxDynamicSharedMemorySize, TC_SMEM);

    h_split_kernel<<<(NN * IND / 4) / 256, 256>>>(h);
    wqkv_prep_kernel<<<dim3(IND / 32, HIDD / 32, 6), dim3(32, 8)>>>(Wq, Wk, Wv);
    wo_prep_kernel<<<dim3(IND / 32, IND / 32), dim3(32, 8)>>>(Wo);

    tc_qkv_kernel<<<dim3(HIDD / 128, NN / 128, 6), 256, TC_SMEM>>>(bq, bk, bv);
    vtrans_kernel<<<dim3(NN / 32, HIDD / 32, NHEAD), dim3(32, 8)>>>();
    tc_scores_kernel<<<dim3(NN / 128, NN / 128, NHEAD), 256, TC_SMEM>>>(adj);
    softmax_kernel<<<dim3(NN, NHEAD), 256>>>();
    tc_attnv_kernel<<<dim3(HIDD / 128, NN / 128, NHEAD * 2), 256, TC_SMEM>>>();
    xreduce_kernel<<<(NN * IND / 4) / 256, 256>>>();
    tc_z_kernel<<<dim3(IND / 128, NN / 128), 256, TC_SMEM>>>(bo);
    lnproj_kernel<<<NN, 128>>>(gamma, beta, Wp, bp, out);
}